// round 1
// baseline (speedup 1.0000x reference)
#include <cuda_runtime.h>
#include <cuda_bf16.h>
#include <math.h>

// Problem constants
#define BB   8
#define CC   128
#define HH   56
#define WW   56
#define HWP  3136          // 56*56
#define REDC 32
#define GRP  8
#define KK   49
#define OCH  392           // GRP*KK
#define HID  512
#define NPIX 25088         // BB*HWP

// LN output, [pixel][channel] layout (row-major M x K for the MLP GEMM)
__device__ float g_ln[(size_t)NPIX * CC];

// ---------------------------------------------------------------------------
// Kernel A: per (b,h) row — conv1 + BN + ReLU + conv2 + involution + LayerNorm
// smem layout (floats):
//   ts   [0,      1824)   : t activations  [32][57]
//   c2s  [1824,  14368)   : conv2 weights [392][32], later reused as x halo
//                           staging [16][7][62] (6944 floats)
//   wgs  [14368, 36320)   : involution weights [392][56]
//   os   [36320, 43616)   : [128][57] — first aliased as x-row cache [128][56],
//                           then involution output for LN
// ---------------------------------------------------------------------------
#define SMA_TS  0
#define SMA_C2S 1824
#define SMA_WGS 14368
#define SMA_OS  36320
#define SMA_TOT 43616
#define SMEM_A  (SMA_TOT * 4)

__global__ __launch_bounds__(256) void kernA(
    const float* __restrict__ x,
    const float* __restrict__ c1w, const float* __restrict__ c1b,
    const float* __restrict__ bng, const float* __restrict__ bnb,
    const float* __restrict__ bnm, const float* __restrict__ bnv,
    const float* __restrict__ c2w, const float* __restrict__ c2b,
    const float* __restrict__ lnw, const float* __restrict__ lnb)
{
    extern __shared__ float sm[];
    float* ts  = sm + SMA_TS;    // [32][57]
    float* c2s = sm + SMA_C2S;   // [392][32] then [16][7][62]
    float* wgs = sm + SMA_WGS;   // [392][56]
    float* os  = sm + SMA_OS;    // [128][57]; aliased as xs [128][56] early
    float* xs  = os;

    __shared__ float mus[56], rss[56];
    __shared__ float psum[4][56], psq[4][56];

    const int b   = blockIdx.x / HH;
    const int h   = blockIdx.x % HH;
    const int tid = threadIdx.x;
    const float* xb = x + (size_t)b * CC * HWP;

    // ---- stage x row (all 128 channels at this h) and conv2 weights ----
    for (int t = tid; t < CC * WW; t += 256) {
        int w = t % WW, c = t / WW;
        xs[c * WW + w] = xb[(size_t)c * HWP + h * WW + w];
    }
    for (int t = tid; t < OCH * REDC; t += 256) c2s[t] = c2w[t];
    __syncthreads();

    // ---- conv1 (128->32) + BN(eval) + ReLU : 4r x 2w tiles, 224 threads ----
    if (tid < 224) {
        int wp = tid % 28, rg = tid / 28;
        int w0 = wp * 2, rb = rg * 4;
        float a[4][2];
        #pragma unroll
        for (int q = 0; q < 4; q++) { a[q][0] = 0.f; a[q][1] = 0.f; }
        #pragma unroll 4
        for (int k4 = 0; k4 < 128; k4 += 4) {
            float xv0[4], xv1[4];
            #pragma unroll
            for (int kk = 0; kk < 4; kk++) {
                xv0[kk] = xs[(k4 + kk) * WW + w0];
                xv1[kk] = xs[(k4 + kk) * WW + w0 + 1];
            }
            #pragma unroll
            for (int q = 0; q < 4; q++) {
                float4 wv = *(const float4*)(c1w + (size_t)(rb + q) * 128 + k4);
                a[q][0] = fmaf(wv.x, xv0[0], a[q][0]); a[q][1] = fmaf(wv.x, xv1[0], a[q][1]);
                a[q][0] = fmaf(wv.y, xv0[1], a[q][0]); a[q][1] = fmaf(wv.y, xv1[1], a[q][1]);
                a[q][0] = fmaf(wv.z, xv0[2], a[q][0]); a[q][1] = fmaf(wv.z, xv1[2], a[q][1]);
                a[q][0] = fmaf(wv.w, xv0[3], a[q][0]); a[q][1] = fmaf(wv.w, xv1[3], a[q][1]);
            }
        }
        #pragma unroll
        for (int q = 0; q < 4; q++) {
            int r = rb + q;
            float sc = bng[r] * rsqrtf(bnv[r] + 1e-5f);
            float v0 = (a[q][0] + c1b[r] - bnm[r]) * sc + bnb[r];
            float v1 = (a[q][1] + c1b[r] - bnm[r]) * sc + bnb[r];
            ts[r * 57 + w0]     = fmaxf(v0, 0.f);
            ts[r * 57 + w0 + 1] = fmaxf(v1, 0.f);
        }
    }
    __syncthreads();

    // ---- conv2 (32->392) : 4o x 2w register tiles ----
    for (int t = tid; t < 98 * 28; t += 256) {
        int wp = t % 28, og = t / 28;
        int w0 = wp * 2, ob = og * 4;
        float a[4][2];
        #pragma unroll
        for (int q = 0; q < 4; q++) { float bb = c2b[ob + q]; a[q][0] = bb; a[q][1] = bb; }
        #pragma unroll
        for (int r4 = 0; r4 < 32; r4 += 4) {
            float tv0[4], tv1[4];
            #pragma unroll
            for (int rr = 0; rr < 4; rr++) {
                tv0[rr] = ts[(r4 + rr) * 57 + w0];
                tv1[rr] = ts[(r4 + rr) * 57 + w0 + 1];
            }
            #pragma unroll
            for (int q = 0; q < 4; q++) {
                float4 wv = *(const float4*)(c2s + (ob + q) * 32 + r4);
                a[q][0] = fmaf(wv.x, tv0[0], a[q][0]); a[q][1] = fmaf(wv.x, tv1[0], a[q][1]);
                a[q][0] = fmaf(wv.y, tv0[1], a[q][0]); a[q][1] = fmaf(wv.y, tv1[1], a[q][1]);
                a[q][0] = fmaf(wv.z, tv0[2], a[q][0]); a[q][1] = fmaf(wv.z, tv1[2], a[q][1]);
                a[q][0] = fmaf(wv.w, tv0[3], a[q][0]); a[q][1] = fmaf(wv.w, tv1[3], a[q][1]);
            }
        }
        #pragma unroll
        for (int q = 0; q < 4; q++) {
            wgs[(ob + q) * WW + w0]     = a[q][0];
            wgs[(ob + q) * WW + w0 + 1] = a[q][1];
        }
    }
    __syncthreads();

    // ---- involution: process channels in 8 chunks of 16 (== one group each),
    //      staging the 7-row x 62-col halo through smem (reuses c2s) ----
    for (int cc = 0; cc < 8; cc++) {
        // load halo: 16 channels x 7 rows x 62 cols (zero padded)
        for (int t = tid; t < 16 * 7 * 62; t += 256) {
            int wq = t % 62;
            int rr = (t / 62) % 7;
            int c2 = t / (62 * 7);
            int hh2 = h + rr - 3;
            int w2i = wq - 3;
            float v = 0.f;
            if ((unsigned)hh2 < 56u && (unsigned)w2i < 56u)
                v = xb[(size_t)(cc * 16 + c2) * HWP + hh2 * WW + w2i];
            c2s[t] = v;
        }
        __syncthreads();
        // 224 threads: each handles one w and 4 channels (wg shared across them)
        if (tid < 224) {
            int w = tid % 56;
            int c2b4 = (tid / 56) * 4;
            const float* wg = wgs + cc * KK * WW + w;   // group == chunk
            float acc[4];
            #pragma unroll
            for (int q = 0; q < 4; q++) acc[q] = 0.f;
            #pragma unroll
            for (int kh = 0; kh < 7; kh++) {
                #pragma unroll
                for (int kw = 0; kw < 7; kw++) {
                    float wv = wg[(kh * 7 + kw) * WW];
                    #pragma unroll
                    for (int q = 0; q < 4; q++)
                        acc[q] = fmaf(wv, c2s[(c2b4 + q) * 434 + kh * 62 + w + kw], acc[q]);
                }
            }
            #pragma unroll
            for (int q = 0; q < 4; q++)
                os[(cc * 16 + c2b4 + q) * 57 + w] = acc[q];
        }
        __syncthreads();
    }

    // ---- LayerNorm stats over 128 channels per pixel ----
    if (tid < 224) {
        int w = tid % 56, part = tid / 56;
        float s = 0.f, s2 = 0.f;
        for (int c = part * 32; c < part * 32 + 32; c++) {
            float v = os[c * 57 + w];
            s += v; s2 += v * v;
        }
        psum[part][w] = s; psq[part][w] = s2;
    }
    __syncthreads();
    if (tid < 56) {
        float s  = psum[0][tid] + psum[1][tid] + psum[2][tid] + psum[3][tid];
        float s2 = psq[0][tid]  + psq[1][tid]  + psq[2][tid]  + psq[3][tid];
        float mu  = s * (1.f / 128.f);
        float var = s2 * (1.f / 128.f) - mu * mu;
        mus[tid] = mu;
        rss[tid] = rsqrtf(var + 1e-6f);
    }
    __syncthreads();

    // ---- write normalized output, [pixel][channel], coalesced in channel ----
    float* dst = g_ln + ((size_t)b * HWP + (size_t)h * WW) * CC;
    for (int t = tid; t < CC * WW; t += 256) {
        int c = t % CC, w = t / CC;
        float v = (os[c * 57 + w] - mus[w]) * rss[w] * lnw[c] + lnb[c];
        dst[(size_t)w * CC + c] = v;
    }
}

// ---------------------------------------------------------------------------
// Kernel B: MLP per 32-pixel tile:  h = gelu(y@w1^T+b1); out = h@w2^T+b2 + x
// smem (floats): ys [32][132] @0, hs [32][68] @4224, w2s [128][64] @6400
// ---------------------------------------------------------------------------
#define SMB_YS  0
#define SMB_HS  4224
#define SMB_W2S 6400
#define SMB_TOT 14592
#define SMEM_B  (SMB_TOT * 4)

__global__ __launch_bounds__(256, 3) void kernB(
    const float* __restrict__ x,
    const float* __restrict__ w1, const float* __restrict__ b1,
    const float* __restrict__ w2, const float* __restrict__ b2,
    float* __restrict__ out)
{
    extern __shared__ float sm[];
    float* ys  = sm + SMB_YS;    // [32][132]
    float* hs  = sm + SMB_HS;    // [32][68]
    float* w2s = sm + SMB_W2S;   // [128][64]

    const int tid = threadIdx.x;
    const size_t p0 = (size_t)blockIdx.x * 32;

    // load 32x128 LN-activations tile (coalesced)
    const float* src = g_ln + p0 * CC;
    for (int t = tid; t < 32 * 128; t += 256) {
        int c = t & 127, p = t >> 7;
        ys[p * 132 + c] = src[t];
    }

    const int tp = tid & 15;          // pixel-pair owner for GEMM1
    const int jb = (tid >> 4) * 4;    // 4 hidden units
    const int pixlo = tid & 31;       // pixel for GEMM2
    const int cg = tid >> 5;          // 16-channel group for GEMM2

    float acc[16];
    #pragma unroll
    for (int i = 0; i < 16; i++) acc[i] = 0.f;

    for (int nb = 0; nb < 8; nb++) {
        const int j0 = nb * 64;
        __syncthreads();              // ys ready / prev iter done with hs,w2s

        // stage w2 tile [128][64]
        for (int t = tid; t < 128 * 64; t += 256)
            w2s[t] = w2[(size_t)(t >> 6) * HID + j0 + (t & 63)];

        // GEMM1: 2 pixels x 4 hidden per thread, K=128
        float ha[2][4];
        #pragma unroll
        for (int p = 0; p < 2; p++)
            #pragma unroll
            for (int j = 0; j < 4; j++) ha[p][j] = b1[j0 + jb + j];
        const float* w1b = w1 + (size_t)(j0 + jb) * 128;
        #pragma unroll 4
        for (int k = 0; k < 128; k += 4) {
            float4 y0 = *(const float4*)(ys + tp * 132 + k);
            float4 y1 = *(const float4*)(ys + (tp + 16) * 132 + k);
            #pragma unroll
            for (int j = 0; j < 4; j++) {
                float4 wv = *(const float4*)(w1b + (size_t)j * 128 + k);
                ha[0][j] = fmaf(y0.x, wv.x, ha[0][j]); ha[1][j] = fmaf(y1.x, wv.x, ha[1][j]);
                ha[0][j] = fmaf(y0.y, wv.y, ha[0][j]); ha[1][j] = fmaf(y1.y, wv.y, ha[1][j]);
                ha[0][j] = fmaf(y0.z, wv.z, ha[0][j]); ha[1][j] = fmaf(y1.z, wv.z, ha[1][j]);
                ha[0][j] = fmaf(y0.w, wv.w, ha[0][j]); ha[1][j] = fmaf(y1.w, wv.w, ha[1][j]);
            }
        }
        // exact-erf GELU, store to hs
        #pragma unroll
        for (int p = 0; p < 2; p++)
            #pragma unroll
            for (int j = 0; j < 4; j++) {
                float a = ha[p][j];
                hs[(tp + p * 16) * 68 + jb + j] =
                    0.5f * a * (1.f + erff(a * 0.70710678118654752f));
            }
        __syncthreads();

        // GEMM2: accumulate 16 output channels for one pixel
        const float* hp  = hs + pixlo * 68;
        const float* wcp = w2s + (cg * 16) * 64;
        #pragma unroll 2
        for (int j = 0; j < 64; j += 4) {
            float4 hv = *(const float4*)(hp + j);
            #pragma unroll
            for (int i = 0; i < 16; i++) {
                float4 wv = *(const float4*)(wcp + i * 64 + j);
                acc[i] = fmaf(hv.x, wv.x, acc[i]);
                acc[i] = fmaf(hv.y, wv.y, acc[i]);
                acc[i] = fmaf(hv.z, wv.z, acc[i]);
                acc[i] = fmaf(hv.w, wv.w, acc[i]);
            }
        }
    }

    // bias + residual + coalesced NCHW store
    const size_t b   = p0 / HWP;
    const size_t hw0 = p0 % HWP;
    #pragma unroll
    for (int i = 0; i < 16; i++) {
        int c = cg * 16 + i;
        size_t idx = (b * CC + c) * HWP + hw0 + pixlo;
        out[idx] = acc[i] + b2[c] + x[idx];
    }
}

// ---------------------------------------------------------------------------
extern "C" void kernel_launch(void* const* d_in, const int* in_sizes, int n_in,
                              void* d_out, int out_size)
{
    const float* x   = (const float*)d_in[0];
    const float* c1w = (const float*)d_in[1];
    const float* c1b = (const float*)d_in[2];
    const float* bng = (const float*)d_in[3];
    const float* bnb = (const float*)d_in[4];
    const float* bnm = (const float*)d_in[5];
    const float* bnv = (const float*)d_in[6];
    const float* c2w = (const float*)d_in[7];
    const float* c2b = (const float*)d_in[8];
    const float* lnw = (const float*)d_in[9];
    const float* lnb = (const float*)d_in[10];
    const float* w1  = (const float*)d_in[11];
    const float* b1  = (const float*)d_in[12];
    const float* w2  = (const float*)d_in[13];
    const float* b2  = (const float*)d_in[14];
    float* out = (float*)d_out;

    cudaFuncSetAttribute(kernA, cudaFuncAttributeMaxDynamicSharedMemorySize, SMEM_A);
    cudaFuncSetAttribute(kernB, cudaFuncAttributeMaxDynamicSharedMemorySize, SMEM_B);

    kernA<<<BB * HH, 256, SMEM_A>>>(x, c1w, c1b, bng, bnb, bnm, bnv,
                                    c2w, c2b, lnw, lnb);
    kernB<<<NPIX / 32, 256, SMEM_B>>>(x, w1, b1, w2, b2, out);
}

// round 2
// speedup vs baseline: 1.5623x; 1.5623x over previous
#include <cuda_runtime.h>
#include <math.h>

#define BB   8
#define CC   128
#define HH   56
#define WW   56
#define HWP  3136
#define REDC 32
#define GRP  8
#define KK   49
#define OCH  392
#define HID  512
#define NPIX 25088

// scratch: involution weights [b][oc][hw], involution output (pre-LN) [pixel][c]
__device__ float g_wgt[(size_t)BB * OCH * HWP];
__device__ float g_inv[(size_t)NPIX * CC];

// ---------------------------------------------------------------------------
// kernW: per (batch, 64-pixel chunk): conv1(128->32)+BN+ReLU then conv2(32->392)
// ---------------------------------------------------------------------------
__global__ __launch_bounds__(256) void kernW(
    const float* __restrict__ x,
    const float* __restrict__ c1w, const float* __restrict__ c1b,
    const float* __restrict__ bng, const float* __restrict__ bnb,
    const float* __restrict__ bnm, const float* __restrict__ bnv,
    const float* __restrict__ c2w, const float* __restrict__ c2b)
{
    __shared__ float xs[128][68];
    __shared__ float ts[32][68];

    const int bIdx = blockIdx.x / 49;
    const int pc   = blockIdx.x % 49;
    const int p0   = pc * 64;
    const int tid  = threadIdx.x;
    const float* xb = x + (size_t)bIdx * CC * HWP + p0;

    // load x tile [128c][64px] coalesced
    for (int t = tid; t < 128 * 16; t += 256) {
        int c = t >> 4, f = t & 15;
        *(float4*)&xs[c][f * 4] = *(const float4*)(xb + (size_t)c * HWP + f * 4);
    }
    __syncthreads();

    const int pxg = tid & 15, px0 = pxg * 4;

    // ---- conv1: 2 rows x 4 px per thread ----
    {
        int r0 = (tid >> 4) * 2;
        float a0[4] = {0.f, 0.f, 0.f, 0.f};
        float a1[4] = {0.f, 0.f, 0.f, 0.f};
        const float* w0p = c1w + (size_t)r0 * 128;
        const float* w1p = w0p + 128;
        #pragma unroll 8
        for (int k4 = 0; k4 < 32; k4++) {
            float wa[4], wb[4];
            *(float4*)wa = *(const float4*)(w0p + k4 * 4);
            *(float4*)wb = *(const float4*)(w1p + k4 * 4);
            #pragma unroll
            for (int kk = 0; kk < 4; kk++) {
                float xv[4];
                *(float4*)xv = *(float4*)&xs[k4 * 4 + kk][px0];
                #pragma unroll
                for (int i = 0; i < 4; i++) {
                    a0[i] = fmaf(wa[kk], xv[i], a0[i]);
                    a1[i] = fmaf(wb[kk], xv[i], a1[i]);
                }
            }
        }
        #pragma unroll
        for (int rr = 0; rr < 2; rr++) {
            int r = r0 + rr;
            float sc = bng[r] * rsqrtf(bnv[r] + 1e-5f);
            float sh = (c1b[r] - bnm[r]) * sc + bnb[r];
            float* ap = rr ? a1 : a0;
            float4 o;
            o.x = fmaxf(fmaf(ap[0], sc, sh), 0.f);
            o.y = fmaxf(fmaf(ap[1], sc, sh), 0.f);
            o.z = fmaxf(fmaf(ap[2], sc, sh), 0.f);
            o.w = fmaxf(fmaf(ap[3], sc, sh), 0.f);
            *(float4*)&ts[r][px0] = o;
        }
    }
    __syncthreads();

    // ---- conv2: 7 chunks of 64 oc (padded 448); 4 oc x 4 px per thread ----
    {
        const int og = tid >> 4;
        for (int ch = 0; ch < 7; ch++) {
            int ocb = ch * 64 + og * 4;
            float a[4][4];
            #pragma unroll
            for (int q = 0; q < 4; q++)
                #pragma unroll
                for (int i = 0; i < 4; i++) a[q][i] = 0.f;
            const float* wr[4];
            #pragma unroll
            for (int q = 0; q < 4; q++)
                wr[q] = c2w + (size_t)(ocb + q < 392 ? ocb + q : 391) * 32;
            #pragma unroll
            for (int k4 = 0; k4 < 8; k4++) {
                float wv[4][4];
                #pragma unroll
                for (int q = 0; q < 4; q++)
                    *(float4*)wv[q] = *(const float4*)(wr[q] + k4 * 4);
                #pragma unroll
                for (int kk = 0; kk < 4; kk++) {
                    float xv[4];
                    *(float4*)xv = *(float4*)&ts[k4 * 4 + kk][px0];
                    #pragma unroll
                    for (int q = 0; q < 4; q++)
                        #pragma unroll
                        for (int i = 0; i < 4; i++)
                            a[q][i] = fmaf(wv[q][kk], xv[i], a[q][i]);
                }
            }
            #pragma unroll
            for (int q = 0; q < 4; q++) {
                int oc = ocb + q;
                if (oc < 392) {
                    float bb = c2b[oc];
                    float4 o = {a[q][0] + bb, a[q][1] + bb, a[q][2] + bb, a[q][3] + bb};
                    *(float4*)(g_wgt + ((size_t)bIdx * OCH + oc) * HWP + p0 + px0) = o;
                }
            }
        }
    }
}

// ---------------------------------------------------------------------------
// kernI: involution per (b,h), looping 8 groups; output [pixel][channel]
// ---------------------------------------------------------------------------
__global__ __launch_bounds__(256) void kernI(const float* __restrict__ x)
{
    __shared__ float hs_[16 * 7 * 62];   // halo, 16 ch x 7 rows x 62 cols
    __shared__ float ws_[49 * 57];       // wgt tile

    const int bIdx = blockIdx.x / 56;
    const int h    = blockIdx.x % 56;
    const int tid  = threadIdx.x;
    const float* xb = x + (size_t)bIdx * CC * HWP;

    for (int g = 0; g < 8; g++) {
        for (int t = tid; t < 49 * 56; t += 256) {
            int k = t / 56, w = t % 56;
            ws_[k * 57 + w] = g_wgt[((size_t)bIdx * OCH + g * 49 + k) * HWP + h * 56 + w];
        }
        for (int t = tid; t < 16 * 7 * 62; t += 256) {
            int wq = t % 62, rr = (t / 62) % 7, c2 = t / 434;
            int h2 = h + rr - 3, w2 = wq - 3;
            float v = 0.f;
            if ((unsigned)h2 < 56u && (unsigned)w2 < 56u)
                v = xb[(size_t)(g * 16 + c2) * HWP + h2 * 56 + w2];
            hs_[t] = v;
        }
        __syncthreads();

        if (tid < 224) {
            const int wq = tid % 28, cq = tid / 28;
            const int w0 = wq * 2, c0 = cq * 2;
            float acc[2][2] = {{0.f, 0.f}, {0.f, 0.f}};
            #pragma unroll
            for (int kh = 0; kh < 7; kh++) {
                float wv0[7], wv1[7];
                #pragma unroll
                for (int kw = 0; kw < 7; kw++) {
                    wv0[kw] = ws_[(kh * 7 + kw) * 57 + w0];
                    wv1[kw] = ws_[(kh * 7 + kw) * 57 + w0 + 1];
                }
                #pragma unroll
                for (int cc2 = 0; cc2 < 2; cc2++) {
                    const float* xr = &hs_[(c0 + cc2) * 434 + kh * 62 + w0];
                    float xw[8];
                    #pragma unroll
                    for (int i = 0; i < 4; i++)
                        *(float2*)&xw[i * 2] = *(const float2*)(xr + i * 2);
                    #pragma unroll
                    for (int kw = 0; kw < 7; kw++) {
                        acc[0][cc2] = fmaf(wv0[kw], xw[kw],     acc[0][cc2]);
                        acc[1][cc2] = fmaf(wv1[kw], xw[kw + 1], acc[1][cc2]);
                    }
                }
            }
            size_t pxb = (size_t)bIdx * HWP + (size_t)h * 56;
            int cbase = g * 16 + c0;
            *(float2*)(g_inv + (pxb + w0)     * CC + cbase) = make_float2(acc[0][0], acc[0][1]);
            *(float2*)(g_inv + (pxb + w0 + 1) * CC + cbase) = make_float2(acc[1][0], acc[1][1]);
        }
        __syncthreads();
    }
}

// ---------------------------------------------------------------------------
// kernM: LN + MLP + residual per 64-pixel tile
// smem: ys[64][132] + hs[64][68] + w2s[128][68]  = 86KB dynamic
// ---------------------------------------------------------------------------
#define SMM_YS  0
#define SMM_HS  (64 * 132)
#define SMM_W2S (64 * 132 + 64 * 68)
#define SMM_TOT (64 * 132 + 64 * 68 + 128 * 68)
#define SMEM_M  (SMM_TOT * 4)

__global__ __launch_bounds__(256, 2) void kernM(
    const float* __restrict__ x,
    const float* __restrict__ w1, const float* __restrict__ b1,
    const float* __restrict__ w2, const float* __restrict__ b2,
    const float* __restrict__ lnw, const float* __restrict__ lnb,
    float* __restrict__ out)
{
    extern __shared__ float sm[];
    float* ys  = sm + SMM_YS;
    float* hsm = sm + SMM_HS;
    float* w2s = sm + SMM_W2S;
    __shared__ float mus[64], rss[64];

    const int tid = threadIdx.x;
    const size_t p0 = (size_t)blockIdx.x * 64;

    // load inv tile [64px][128c]
    const float* src = g_inv + p0 * CC;
    for (int t = tid; t < 64 * 32; t += 256) {
        int p = t >> 5, f = t & 31;
        *(float4*)&ys[p * 132 + f * 4] = *(const float4*)(src + (size_t)p * 128 + f * 4);
    }
    __syncthreads();

    // LN stats: 4 lanes per pixel, 32 channels each
    {
        int p = tid >> 2, l = tid & 3;
        float s = 0.f, s2 = 0.f;
        const float* yp = ys + p * 132 + l * 32;
        #pragma unroll 8
        for (int i = 0; i < 32; i++) { float v = yp[i]; s += v; s2 = fmaf(v, v, s2); }
        s  += __shfl_xor_sync(0xffffffffu, s, 1);  s2 += __shfl_xor_sync(0xffffffffu, s2, 1);
        s  += __shfl_xor_sync(0xffffffffu, s, 2);  s2 += __shfl_xor_sync(0xffffffffu, s2, 2);
        if (l == 0) {
            float mu = s * (1.f / 128.f);
            float var = s2 * (1.f / 128.f) - mu * mu;
            mus[p] = mu;
            rss[p] = rsqrtf(var + 1e-6f);
        }
    }
    __syncthreads();
    for (int t = tid; t < 64 * 128; t += 256) {
        int p = t >> 7, c = t & 127;
        ys[p * 132 + c] = (ys[p * 132 + c] - mus[p]) * rss[p] * lnw[c] + lnb[c];
    }

    const int pxg = tid & 15;        // pixels pxg + {0,16,32,48}
    const int hg  = tid >> 4;        // GEMM1: 4 hidden; GEMM2: 8 channels

    float acc[4][8];
    #pragma unroll
    for (int p = 0; p < 4; p++)
        #pragma unroll
        for (int i = 0; i < 8; i++) acc[p][i] = 0.f;

    __syncthreads();   // ys normalized

    for (int nb = 0; nb < 8; nb++) {
        const int j0 = nb * 64;

        // stage w2 tile [128c][64j]
        for (int t = tid; t < 128 * 16; t += 256) {
            int c = t >> 4, f = t & 15;
            *(float4*)&w2s[c * 68 + f * 4] = *(const float4*)(w2 + (size_t)c * HID + j0 + f * 4);
        }

        // GEMM1: 4px x 4h, K=128
        float ha[4][4];
        {
            float bv[4];
            #pragma unroll
            for (int j = 0; j < 4; j++) bv[j] = b1[j0 + hg * 4 + j];
            #pragma unroll
            for (int p = 0; p < 4; p++)
                #pragma unroll
                for (int j = 0; j < 4; j++) ha[p][j] = bv[j];
        }
        const float* w1b = w1 + (size_t)(j0 + hg * 4) * 128;
        #pragma unroll 4
        for (int k4 = 0; k4 < 32; k4++) {
            float yv[4][4], wv[4][4];
            #pragma unroll
            for (int p = 0; p < 4; p++)
                *(float4*)yv[p] = *(float4*)&ys[(pxg + p * 16) * 132 + k4 * 4];
            #pragma unroll
            for (int j = 0; j < 4; j++)
                *(float4*)wv[j] = *(const float4*)(w1b + (size_t)j * 128 + k4 * 4);
            #pragma unroll
            for (int kk = 0; kk < 4; kk++)
                #pragma unroll
                for (int p = 0; p < 4; p++)
                    #pragma unroll
                    for (int j = 0; j < 4; j++)
                        ha[p][j] = fmaf(yv[p][kk], wv[j][kk], ha[p][j]);
        }
        // exact-erf GELU -> hs
        #pragma unroll
        for (int p = 0; p < 4; p++) {
            float4 o;
            float* op = (float*)&o;
            #pragma unroll
            for (int j = 0; j < 4; j++) {
                float a = ha[p][j];
                op[j] = 0.5f * a * (1.f + erff(a * 0.70710678118654752f));
            }
            *(float4*)&hsm[(pxg + p * 16) * 68 + hg * 4] = o;
        }
        __syncthreads();

        // GEMM2: 4px x 8c, K=64
        #pragma unroll 4
        for (int j4 = 0; j4 < 16; j4++) {
            float hv[4][4];
            #pragma unroll
            for (int p = 0; p < 4; p++)
                *(float4*)hv[p] = *(float4*)&hsm[(pxg + p * 16) * 68 + j4 * 4];
            #pragma unroll
            for (int i = 0; i < 8; i++) {
                float wv[4];
                *(float4*)wv = *(float4*)&w2s[(hg * 8 + i) * 68 + j4 * 4];
                #pragma unroll
                for (int p = 0; p < 4; p++) {
                    acc[p][i] = fmaf(hv[p][0], wv[0], acc[p][i]);
                    acc[p][i] = fmaf(hv[p][1], wv[1], acc[p][i]);
                    acc[p][i] = fmaf(hv[p][2], wv[2], acc[p][i]);
                    acc[p][i] = fmaf(hv[p][3], wv[3], acc[p][i]);
                }
            }
        }
        __syncthreads();
    }

    // epilogue: bias + residual, NCHW store
    const size_t bIdx = p0 / HWP;
    const size_t hw0  = p0 % HWP;
    #pragma unroll
    for (int i = 0; i < 8; i++) {
        int c = hg * 8 + i;
        float bb = b2[c];
        #pragma unroll
        for (int p = 0; p < 4; p++) {
            size_t idx = (bIdx * CC + c) * HWP + hw0 + pxg + p * 16;
            out[idx] = acc[p][i] + bb + x[idx];
        }
    }
}

// ---------------------------------------------------------------------------
extern "C" void kernel_launch(void* const* d_in, const int* in_sizes, int n_in,
                              void* d_out, int out_size)
{
    const float* x   = (const float*)d_in[0];
    const float* c1w = (const float*)d_in[1];
    const float* c1b = (const float*)d_in[2];
    const float* bng = (const float*)d_in[3];
    const float* bnb = (const float*)d_in[4];
    const float* bnm = (const float*)d_in[5];
    const float* bnv = (const float*)d_in[6];
    const float* c2w = (const float*)d_in[7];
    const float* c2b = (const float*)d_in[8];
    const float* lnw = (const float*)d_in[9];
    const float* lnb = (const float*)d_in[10];
    const float* w1  = (const float*)d_in[11];
    const float* b1  = (const float*)d_in[12];
    const float* w2  = (const float*)d_in[13];
    const float* b2  = (const float*)d_in[14];
    float* out = (float*)d_out;

    cudaFuncSetAttribute(kernM, cudaFuncAttributeMaxDynamicSharedMemorySize, SMEM_M);

    kernW<<<BB * 49, 256>>>(x, c1w, c1b, bng, bnb, bnm, bnv, c2w, c2b);
    kernI<<<BB * HH, 256>>>(x);
    kernM<<<NPIX / 64, 256, SMEM_M>>>(x, w1, b1, w2, b2, lnw, lnb, out);
}

// round 4
// speedup vs baseline: 1.6677x; 1.0674x over previous
#include <cuda_runtime.h>
#include <cuda_bf16.h>
#include <math.h>
#include <stdint.h>

#define BB   8
#define CC   128
#define HH   56
#define WW   56
#define HWP  3136
#define REDC 32
#define GRP  8
#define KK   49
#define OCH  392
#define HID  512
#define NPIX 25088

// scratch
__device__ float g_wgt[(size_t)BB * OCH * HWP];
__device__ float g_inv[(size_t)NPIX * CC];
// pre-split bf16 weights (hi/lo), layouts already [N][K]
__device__ __nv_bfloat16 g_w1H[HID * CC], g_w1L[HID * CC];
__device__ __nv_bfloat16 g_w2H[CC * HID], g_w2L[CC * HID];

// ======================== helpers ========================
__device__ __forceinline__ uint32_t smem_to_u32(const void* p) {
    uint32_t a;
    asm("{ .reg .u64 t; cvta.to.shared.u64 t, %1; cvt.u32.u64 %0, t; }"
        : "=r"(a) : "l"(p));
    return a;
}
__device__ __forceinline__ void ldsm4(uint32_t r[4], uint32_t addr) {
    asm volatile("ldmatrix.sync.aligned.m8n8.x4.shared.b16 {%0,%1,%2,%3}, [%4];"
        : "=r"(r[0]), "=r"(r[1]), "=r"(r[2]), "=r"(r[3]) : "r"(addr));
}
__device__ __forceinline__ void mma16816(float c[4], const uint32_t a[4],
                                         uint32_t b0, uint32_t b1) {
    asm volatile(
        "mma.sync.aligned.m16n8k16.row.col.f32.bf16.bf16.f32 "
        "{%0,%1,%2,%3}, {%4,%5,%6,%7}, {%8,%9}, {%0,%1,%2,%3};"
        : "+f"(c[0]), "+f"(c[1]), "+f"(c[2]), "+f"(c[3])
        : "r"(a[0]), "r"(a[1]), "r"(a[2]), "r"(a[3]), "r"(b0), "r"(b1));
}
__device__ __forceinline__ void split_pack(float v0, float v1, uint32_t& hi, uint32_t& lo) {
    __nv_bfloat16 h0 = __float2bfloat16(v0);
    __nv_bfloat16 h1 = __float2bfloat16(v1);
    __nv_bfloat16 l0 = __float2bfloat16(v0 - __bfloat162float(h0));
    __nv_bfloat16 l1 = __float2bfloat16(v1 - __bfloat162float(h1));
    __nv_bfloat162 hp; hp.x = h0; hp.y = h1;
    __nv_bfloat162 lp; lp.x = l0; lp.y = l1;
    hi = *(uint32_t*)&hp; lo = *(uint32_t*)&lp;
}

// ---------------------------------------------------------------------------
// kernP: split w1/w2 into bf16 hi/lo
// ---------------------------------------------------------------------------
__global__ __launch_bounds__(256) void kernP(const float* __restrict__ w1,
                                             const float* __restrict__ w2)
{
    int i = blockIdx.x * 256 + threadIdx.x;   // 65536
    float v = w1[i];
    __nv_bfloat16 h = __float2bfloat16(v);
    g_w1H[i] = h;
    g_w1L[i] = __float2bfloat16(v - __bfloat162float(h));
    v = w2[i];
    h = __float2bfloat16(v);
    g_w2H[i] = h;
    g_w2L[i] = __float2bfloat16(v - __bfloat162float(h));
}

// ---------------------------------------------------------------------------
// kernW: conv1(128->32)+BN+ReLU then conv2(32->392), smem-staged weights
// ---------------------------------------------------------------------------
#define WXS 0
#define WTS (128 * 68)
#define WWS (128 * 68 + 32 * 68)
#define SMEM_W ((128 * 68 + 32 * 68 + 392 * 32) * 4)

__global__ __launch_bounds__(256, 2) void kernW(
    const float* __restrict__ x,
    const float* __restrict__ c1w, const float* __restrict__ c1b,
    const float* __restrict__ bng, const float* __restrict__ bnb,
    const float* __restrict__ bnm, const float* __restrict__ bnv,
    const float* __restrict__ c2w, const float* __restrict__ c2b)
{
    extern __shared__ float smw[];
    float* xs = smw + WXS;
    float* ts = smw + WTS;
    float* ws = smw + WWS;

    const int bIdx = blockIdx.x / 49;
    const int pc   = blockIdx.x % 49;
    const int p0   = pc * 64;
    const int tid  = threadIdx.x;
    const float* xb = x + (size_t)bIdx * CC * HWP + p0;

    for (int t = tid; t < 128 * 16; t += 256) {
        int c = t >> 4, f = t & 15;
        *(float4*)&xs[c * 68 + f * 4] = *(const float4*)(xb + (size_t)c * HWP + f * 4);
    }
    for (int t = tid; t < 392 * 8; t += 256)
        *(float4*)&ws[t * 4] = *(const float4*)(c2w + t * 4);
    __syncthreads();

    const int pxg = tid & 15, px0 = pxg * 4;

    // conv1: 2 rows x 4 px
    {
        int r0 = (tid >> 4) * 2;
        float a0[4] = {0.f, 0.f, 0.f, 0.f};
        float a1[4] = {0.f, 0.f, 0.f, 0.f};
        const float* w0p = c1w + (size_t)r0 * 128;
        const float* w1p = w0p + 128;
        #pragma unroll 8
        for (int k4 = 0; k4 < 32; k4++) {
            float wa[4], wb[4];
            *(float4*)wa = *(const float4*)(w0p + k4 * 4);
            *(float4*)wb = *(const float4*)(w1p + k4 * 4);
            #pragma unroll
            for (int kk = 0; kk < 4; kk++) {
                float xv[4];
                *(float4*)xv = *(float4*)&xs[(k4 * 4 + kk) * 68 + px0];
                #pragma unroll
                for (int i = 0; i < 4; i++) {
                    a0[i] = fmaf(wa[kk], xv[i], a0[i]);
                    a1[i] = fmaf(wb[kk], xv[i], a1[i]);
                }
            }
        }
        #pragma unroll
        for (int rr = 0; rr < 2; rr++) {
            int r = r0 + rr;
            float sc = bng[r] * rsqrtf(bnv[r] + 1e-5f);
            float sh = (c1b[r] - bnm[r]) * sc + bnb[r];
            float* ap = rr ? a1 : a0;
            float4 o;
            o.x = fmaxf(fmaf(ap[0], sc, sh), 0.f);
            o.y = fmaxf(fmaf(ap[1], sc, sh), 0.f);
            o.z = fmaxf(fmaf(ap[2], sc, sh), 0.f);
            o.w = fmaxf(fmaf(ap[3], sc, sh), 0.f);
            *(float4*)&ts[r * 68 + px0] = o;
        }
    }
    __syncthreads();

    // conv2: 7 chunks of 64 oc, 4 oc x 4 px
    {
        const int og = tid >> 4;
        for (int ch = 0; ch < 7; ch++) {
            int ocb = ch * 64 + og * 4;
            float a[4][4];
            #pragma unroll
            for (int q = 0; q < 4; q++)
                #pragma unroll
                for (int i = 0; i < 4; i++) a[q][i] = 0.f;
            int oc0 = ocb < 388 ? ocb : 388;
            #pragma unroll
            for (int k4 = 0; k4 < 8; k4++) {
                float wv[4][4];
                #pragma unroll
                for (int q = 0; q < 4; q++)
                    *(float4*)wv[q] = *(float4*)&ws[(oc0 + q) * 32 + k4 * 4];
                #pragma unroll
                for (int kk = 0; kk < 4; kk++) {
                    float xv[4];
                    *(float4*)xv = *(float4*)&ts[(k4 * 4 + kk) * 68 + px0];
                    #pragma unroll
                    for (int q = 0; q < 4; q++)
                        #pragma unroll
                        for (int i = 0; i < 4; i++)
                            a[q][i] = fmaf(wv[q][kk], xv[i], a[q][i]);
                }
            }
            #pragma unroll
            for (int q = 0; q < 4; q++) {
                int oc = oc0 + q;
                if (ocb + q < 392) {
                    float bb = c2b[oc];
                    float4 o = {a[q][0] + bb, a[q][1] + bb, a[q][2] + bb, a[q][3] + bb};
                    *(float4*)(g_wgt + ((size_t)bIdx * OCH + oc) * HWP + p0 + px0) = o;
                }
            }
        }
    }
}

// ---------------------------------------------------------------------------
// kernI: involution per (b,h)
// ---------------------------------------------------------------------------
__global__ __launch_bounds__(256) void kernI(const float* __restrict__ x)
{
    __shared__ float hs_[16 * 7 * 62];
    __shared__ float ws_[49 * 57];

    const int bIdx = blockIdx.x / 56;
    const int h    = blockIdx.x % 56;
    const int tid  = threadIdx.x;
    const float* xb = x + (size_t)bIdx * CC * HWP;

    for (int g = 0; g < 8; g++) {
        for (int t = tid; t < 49 * 56; t += 256) {
            int k = t / 56, w = t % 56;
            ws_[k * 57 + w] = g_wgt[((size_t)bIdx * OCH + g * 49 + k) * HWP + h * 56 + w];
        }
        for (int t = tid; t < 16 * 7 * 62; t += 256) {
            int wq = t % 62, rr = (t / 62) % 7, c2 = t / 434;
            int h2 = h + rr - 3, w2 = wq - 3;
            float v = 0.f;
            if ((unsigned)h2 < 56u && (unsigned)w2 < 56u)
                v = xb[(size_t)(g * 16 + c2) * HWP + h2 * 56 + w2];
            hs_[t] = v;
        }
        __syncthreads();

        if (tid < 224) {
            const int wq = tid % 28, cq = tid / 28;
            const int w0 = wq * 2, c0 = cq * 2;
            float acc[2][2] = {{0.f, 0.f}, {0.f, 0.f}};
            #pragma unroll
            for (int kh = 0; kh < 7; kh++) {
                float wv0[7], wv1[7];
                #pragma unroll
                for (int kw = 0; kw < 7; kw++) {
                    wv0[kw] = ws_[(kh * 7 + kw) * 57 + w0];
                    wv1[kw] = ws_[(kh * 7 + kw) * 57 + w0 + 1];
                }
                #pragma unroll
                for (int cc2 = 0; cc2 < 2; cc2++) {
                    const float* xr = &hs_[(c0 + cc2) * 434 + kh * 62 + w0];
                    float xw[8];
                    #pragma unroll
                    for (int i = 0; i < 4; i++)
                        *(float2*)&xw[i * 2] = *(const float2*)(xr + i * 2);
                    #pragma unroll
                    for (int kw = 0; kw < 7; kw++) {
                        acc[0][cc2] = fmaf(wv0[kw], xw[kw],     acc[0][cc2]);
                        acc[1][cc2] = fmaf(wv1[kw], xw[kw + 1], acc[1][cc2]);
                    }
                }
            }
            size_t pxb = (size_t)bIdx * HWP + (size_t)h * 56;
            int cbase = g * 16 + c0;
            *(float2*)(g_inv + (pxb + w0)     * CC + cbase) = make_float2(acc[0][0], acc[0][1]);
            *(float2*)(g_inv + (pxb + w0 + 1) * CC + cbase) = make_float2(acc[1][0], acc[1][1]);
        }
        __syncthreads();
    }
}

// ---------------------------------------------------------------------------
// kernM: LN + MLP via mma.sync bf16 split + residual. 128-pixel CTAs, 8 warps.
// smem layout (bytes):
//   b1s 512f @0, b2s 128f @2048
//   ysH [128][272B pitch] @2560, ysL @+34816
//   hsH [128][144B pitch], hsL
//   w1H [64][272B], w1L ; w2H [128][144B], w2L
// ---------------------------------------------------------------------------
#define MS_B1  0
#define MS_B2  2048
#define MS_YSH 2560
#define MS_YSL (MS_YSH + 34816)
#define MS_HSH (MS_YSL + 34816)
#define MS_HSL (MS_HSH + 18432)
#define MS_W1H (MS_HSL + 18432)
#define MS_W1L (MS_W1H + 17408)
#define MS_W2H (MS_W1L + 17408)
#define MS_W2L (MS_W2H + 18432)
#define SMEM_M (MS_W2L + 18432)

__global__ __launch_bounds__(256, 1) void kernM(
    const float* __restrict__ x,
    const float* __restrict__ b1, const float* __restrict__ b2,
    const float* __restrict__ lnw, const float* __restrict__ lnb,
    float* __restrict__ out)
{
    extern __shared__ char smraw[];
    const uint32_t sb = smem_to_u32(smraw);
    float* b1s = (float*)(smraw + MS_B1);
    float* b2s = (float*)(smraw + MS_B2);

    const int tid = threadIdx.x;
    const int wid = tid >> 5;
    const int l   = tid & 31;
    const size_t p0 = (size_t)blockIdx.x * 128;

    for (int t = tid; t < 512; t += 256) b1s[t] = b1[t];
    if (tid < 128) b2s[tid] = b2[tid];

    // ---- LN + bf16 hi/lo staging of ys ----
    {
        const int px = tid >> 1, half = tid & 1;
        const float* src = g_inv + (p0 + px) * CC + half * 64;
        float s = 0.f, s2 = 0.f;
        #pragma unroll 4
        for (int i = 0; i < 64; i += 4) {
            float4 v = *(const float4*)(src + i);
            s += v.x + v.y + v.z + v.w;
            s2 = fmaf(v.x, v.x, s2); s2 = fmaf(v.y, v.y, s2);
            s2 = fmaf(v.z, v.z, s2); s2 = fmaf(v.w, v.w, s2);
        }
        s  += __shfl_xor_sync(0xffffffffu, s, 1);
        s2 += __shfl_xor_sync(0xffffffffu, s2, 1);
        float mu  = s * (1.f / 128.f);
        float var = s2 * (1.f / 128.f) - mu * mu;
        float rs  = rsqrtf(var + 1e-6f);
        #pragma unroll 4
        for (int i = 0; i < 64; i += 2) {
            int k = half * 64 + i;
            float y0 = (src[i]     - mu) * rs * lnw[k]     + lnb[k];
            float y1 = (src[i + 1] - mu) * rs * lnw[k + 1] + lnb[k + 1];
            uint32_t hi, lo;
            split_pack(y0, y1, hi, lo);
            *(uint32_t*)(smraw + MS_YSH + px * 272 + k * 2) = hi;
            *(uint32_t*)(smraw + MS_YSL + px * 272 + k * 2) = lo;
        }
    }
    __syncthreads();

    const int m0   = wid * 16;
    const int r_l  = l & 15;
    const int koff = (l >> 4) * 16;

    // preload A-hi fragments for GEMM1 (ys is stable across chunks)
    uint32_t aH[8][4];
    const uint32_t aBaseH = sb + MS_YSH + (m0 + r_l) * 272 + koff;
    const uint32_t aBaseL = sb + MS_YSL + (m0 + r_l) * 272 + koff;
    #pragma unroll
    for (int ks = 0; ks < 8; ks++) ldsm4(aH[ks], aBaseH + ks * 32);

    float acc2[16][4];
    #pragma unroll
    for (int n = 0; n < 16; n++)
        #pragma unroll
        for (int q = 0; q < 4; q++) acc2[n][q] = 0.f;

    const uint32_t w1bH = sb + MS_W1H + r_l * 272 + koff;
    const uint32_t w1bL = sb + MS_W1L + r_l * 272 + koff;
    const uint32_t hBH  = sb + MS_HSH + (m0 + r_l) * 144 + koff;
    const uint32_t hBL  = sb + MS_HSL + (m0 + r_l) * 144 + koff;
    const uint32_t w2bH = sb + MS_W2H + r_l * 144 + koff;
    const uint32_t w2bL = sb + MS_W2L + r_l * 144 + koff;

    for (int nb = 0; nb < 8; nb++) {
        const int j0 = nb * 64;
        __syncthreads();   // previous chunk done reading weight tiles

        // stage w1 chunk [64][128] and w2 chunk [128][64] (bf16 hi/lo)
        {
            const uint32_t* g1h = (const uint32_t*)(g_w1H + (size_t)j0 * 128);
            const uint32_t* g1l = (const uint32_t*)(g_w1L + (size_t)j0 * 128);
            uint32_t* s1h = (uint32_t*)(smraw + MS_W1H);
            uint32_t* s1l = (uint32_t*)(smraw + MS_W1L);
            for (int t = tid; t < 4096; t += 256) {
                int row = t >> 6, col = t & 63;
                s1h[row * 68 + col] = g1h[row * 64 + col];
                s1l[row * 68 + col] = g1l[row * 64 + col];
            }
            const uint32_t* g2h = (const uint32_t*)g_w2H;
            const uint32_t* g2l = (const uint32_t*)g_w2L;
            uint32_t* s2h = (uint32_t*)(smraw + MS_W2H);
            uint32_t* s2l = (uint32_t*)(smraw + MS_W2L);
            const int c0 = j0 >> 1;   // u32 col offset
            for (int t = tid; t < 4096; t += 256) {
                int row = t >> 5, col = t & 31;
                s2h[row * 36 + col] = g2h[row * 256 + c0 + col];
                s2l[row * 36 + col] = g2l[row * 256 + c0 + col];
            }
        }
        __syncthreads();

        // ---- GEMM1: c1[16x64] = ys @ w1chunk^T (hi*hi + hi*lo + lo*hi) ----
        float c1[8][4];
        #pragma unroll
        for (int n = 0; n < 8; n++)
            #pragma unroll
            for (int q = 0; q < 4; q++) c1[n][q] = 0.f;

        #pragma unroll
        for (int ks = 0; ks < 8; ks++) {
            uint32_t aL[4];
            ldsm4(aL, aBaseL + ks * 32);
            #pragma unroll
            for (int ntp = 0; ntp < 4; ntp++) {
                uint32_t bh[4], bl[4];
                ldsm4(bh, w1bH + ntp * 4352 + ks * 32);
                ldsm4(bl, w1bL + ntp * 4352 + ks * 32);
                mma16816(c1[2 * ntp],     aH[ks], bh[0], bh[2]);
                mma16816(c1[2 * ntp],     aH[ks], bl[0], bl[2]);
                mma16816(c1[2 * ntp],     aL,     bh[0], bh[2]);
                mma16816(c1[2 * ntp + 1], aH[ks], bh[1], bh[3]);
                mma16816(c1[2 * ntp + 1], aH[ks], bl[1], bl[3]);
                mma16816(c1[2 * ntp + 1], aL,     bh[1], bh[3]);
            }
        }

        // ---- bias + exact GELU -> hs (hi/lo) ----
        {
            const int r0 = m0 + (l >> 2);
            const int cl = (l & 3) * 2;
            #pragma unroll
            for (int nt = 0; nt < 8; nt++) {
                int j = nt * 8 + cl;
                float2 bv = *(const float2*)&b1s[j0 + j];
                float v0 = c1[nt][0] + bv.x;
                float v1 = c1[nt][1] + bv.y;
                float v2 = c1[nt][2] + bv.x;
                float v3 = c1[nt][3] + bv.y;
                float g0 = 0.5f * v0 * (1.f + erff(v0 * 0.70710678118654752f));
                float g1 = 0.5f * v1 * (1.f + erff(v1 * 0.70710678118654752f));
                float g2 = 0.5f * v2 * (1.f + erff(v2 * 0.70710678118654752f));
                float g3 = 0.5f * v3 * (1.f + erff(v3 * 0.70710678118654752f));
                uint32_t hi, lo;
                split_pack(g0, g1, hi, lo);
                *(uint32_t*)(smraw + MS_HSH + r0 * 144 + j * 2) = hi;
                *(uint32_t*)(smraw + MS_HSL + r0 * 144 + j * 2) = lo;
                split_pack(g2, g3, hi, lo);
                *(uint32_t*)(smraw + MS_HSH + (r0 + 8) * 144 + j * 2) = hi;
                *(uint32_t*)(smraw + MS_HSL + (r0 + 8) * 144 + j * 2) = lo;
            }
        }
        __syncwarp();

        // ---- GEMM2: acc2[16x128] += hs @ w2chunk^T ----
        #pragma unroll
        for (int ks = 0; ks < 4; ks++) {
            uint32_t a2h[4], a2l[4];
            ldsm4(a2h, hBH + ks * 32);
            ldsm4(a2l, hBL + ks * 32);
            #pragma unroll
            for (int ntp = 0; ntp < 8; ntp++) {
                uint32_t bh[4], bl[4];
                ldsm4(bh, w2bH + ntp * 2304 + ks * 32);
                ldsm4(bl, w2bL + ntp * 2304 + ks * 32);
                mma16816(acc2[2 * ntp],     a2h, bh[0], bh[2]);
                mma16816(acc2[2 * ntp],     a2h, bl[0], bl[2]);
                mma16816(acc2[2 * ntp],     a2l, bh[0], bh[2]);
                mma16816(acc2[2 * ntp + 1], a2h, bh[1], bh[3]);
                mma16816(acc2[2 * ntp + 1], a2h, bl[1], bl[3]);
                mma16816(acc2[2 * ntp + 1], a2l, bh[1], bh[3]);
            }
        }
    }

    // ---- epilogue: + b2 + x, NCHW store ----
    {
        const int r0 = m0 + (l >> 2);
        const int cl = (l & 3) * 2;
        #pragma unroll
        for (int q2 = 0; q2 < 2; q2++) {
            int row = r0 + q2 * 8;
            size_t gpx = p0 + row;
            size_t bI = gpx / HWP, hw = gpx % HWP;
            const float* xb = x + bI * CC * HWP + hw;
            float* ob = out + bI * CC * HWP + hw;
            #pragma unroll
            for (int nt = 0; nt < 16; nt++) {
                int c = nt * 8 + cl;
                ob[(size_t)c * HWP]       = acc2[nt][q2 * 2]     + b2s[c]     + xb[(size_t)c * HWP];
                ob[(size_t)(c + 1) * HWP] = acc2[nt][q2 * 2 + 1] + b2s[c + 1] + xb[(size_t)(c + 1) * HWP];
            }
        }
    }
}

// ---------------------------------------------------------------------------
extern "C" void kernel_launch(void* const* d_in, const int* in_sizes, int n_in,
                              void* d_out, int out_size)
{
    const float* x   = (const float*)d_in[0];
    const float* c1w = (const float*)d_in[1];
    const float* c1b = (const float*)d_in[2];
    const float* bng = (const float*)d_in[3];
    const float* bnb = (const float*)d_in[4];
    const float* bnm = (const float*)d_in[5];
    const float* bnv = (const float*)d_in[6];
    const float* c2w = (const float*)d_in[7];
    const float* c2b = (const float*)d_in[8];
    const float* lnw = (const float*)d_in[9];
    const float* lnb = (const float*)d_in[10];
    const float* w1  = (const float*)d_in[11];
    const float* b1  = (const float*)d_in[12];
    const float* w2  = (const float*)d_in[13];
    const float* b2  = (const float*)d_in[14];
    float* out = (float*)d_out;

    cudaFuncSetAttribute(kernW, cudaFuncAttributeMaxDynamicSharedMemorySize, SMEM_W);
    cudaFuncSetAttribute(kernM, cudaFuncAttributeMaxDynamicSharedMemorySize, SMEM_M);

    kernP<<<256, 256>>>(w1, w2);
    kernW<<<BB * 49, 256, SMEM_W>>>(x, c1w, c1b, bng, bnb, bnm, bnv, c2w, c2b);
    kernI<<<BB * HH, 256>>>(x);
    kernM<<<NPIX / 128, 256, SMEM_M>>>(x, b1, b2, lnw, lnb, out);
}

// round 5
// speedup vs baseline: 1.9613x; 1.1761x over previous
#include <cuda_runtime.h>
#include <cuda_bf16.h>
#include <math.h>
#include <stdint.h>

#define BB   8
#define CC   128
#define HH   56
#define WW   56
#define HWP  3136
#define REDC 32
#define GRP  8
#define KK   49
#define OCH  392
#define HID  512
#define NPIX 25088

// scratch
__device__ float g_wgt[(size_t)BB * OCH * HWP];
__device__ float g_inv[(size_t)NPIX * CC];
// weights pre-permuted into mma B-fragment layout:
// w1f: [chunk(8)][ktile(8)][ntile(8)][lane(32)] of uint4 (hi_b0,hi_b1,lo_b0,lo_b1)
// w2f: [chunk(8)][ktile(4)][ntile(16)][lane(32)]
__device__ uint4 g_w1f[8 * 8 * 8 * 32];
__device__ uint4 g_w2f[8 * 4 * 16 * 32];

// ======================== helpers ========================
__device__ __forceinline__ uint32_t smem_to_u32(const void* p) {
    uint32_t a;
    asm("{ .reg .u64 t; cvta.to.shared.u64 t, %1; cvt.u32.u64 %0, t; }"
        : "=r"(a) : "l"(p));
    return a;
}
__device__ __forceinline__ void ldsm4(uint32_t r[4], uint32_t addr) {
    asm volatile("ldmatrix.sync.aligned.m8n8.x4.shared.b16 {%0,%1,%2,%3}, [%4];"
        : "=r"(r[0]), "=r"(r[1]), "=r"(r[2]), "=r"(r[3]) : "r"(addr));
}
__device__ __forceinline__ void mma16816(float c[4], const uint32_t a[4],
                                         uint32_t b0, uint32_t b1) {
    asm volatile(
        "mma.sync.aligned.m16n8k16.row.col.f32.bf16.bf16.f32 "
        "{%0,%1,%2,%3}, {%4,%5,%6,%7}, {%8,%9}, {%0,%1,%2,%3};"
        : "+f"(c[0]), "+f"(c[1]), "+f"(c[2]), "+f"(c[3])
        : "r"(a[0]), "r"(a[1]), "r"(a[2]), "r"(a[3]), "r"(b0), "r"(b1));
}
__device__ __forceinline__ void split_pack(float v0, float v1, uint32_t& hi, uint32_t& lo) {
    __nv_bfloat16 h0 = __float2bfloat16(v0);
    __nv_bfloat16 h1 = __float2bfloat16(v1);
    __nv_bfloat16 l0 = __float2bfloat16(v0 - __bfloat162float(h0));
    __nv_bfloat16 l1 = __float2bfloat16(v1 - __bfloat162float(h1));
    __nv_bfloat162 hp; hp.x = h0; hp.y = h1;
    __nv_bfloat162 lp; lp.x = l0; lp.y = l1;
    hi = *(uint32_t*)&hp; lo = *(uint32_t*)&lp;
}
__device__ __forceinline__ uint32_t pack_bf2(float v0, float v1) {
    __nv_bfloat162 p; p.x = __float2bfloat16(v0); p.y = __float2bfloat16(v1);
    return *(uint32_t*)&p;
}

// ---------------------------------------------------------------------------
// kernP: permute w1/w2 into bf16 hi/lo mma fragments
// ---------------------------------------------------------------------------
__global__ __launch_bounds__(256) void kernP(const float* __restrict__ w1,
                                             const float* __restrict__ w2)
{
    int idx = blockIdx.x * 256 + threadIdx.x;   // [0, 32768)
    float v00, v01, v10, v11;
    uint4* dst;
    if (idx < 16384) {
        int l  = idx & 31;
        int nt = (idx >> 5) & 7;
        int kt = (idx >> 8) & 7;
        int c  = idx >> 11;
        int n = c * 64 + nt * 8 + (l >> 2);
        int k = kt * 16 + (l & 3) * 2;
        const float* p = w1 + (size_t)n * 128 + k;
        v00 = p[0]; v01 = p[1]; v10 = p[8]; v11 = p[9];
        dst = g_w1f + idx;
    } else {
        int i2 = idx - 16384;
        int l   = i2 & 31;
        int nt  = (i2 >> 5) & 15;
        int kt2 = (i2 >> 9) & 3;
        int nb  = i2 >> 11;
        int n = nt * 8 + (l >> 2);
        int k = nb * 64 + kt2 * 16 + (l & 3) * 2;
        const float* p = w2 + (size_t)n * 512 + k;
        v00 = p[0]; v01 = p[1]; v10 = p[8]; v11 = p[9];
        dst = g_w2f + i2;
    }
    uint32_t h0, l0, h1, l1;
    split_pack(v00, v01, h0, l0);
    split_pack(v10, v11, h1, l1);
    *dst = make_uint4(h0, h1, l0, l1);
}

// ---------------------------------------------------------------------------
// kernW: conv1(128->32)+BN+ReLU then conv2(32->392), smem-staged weights
// ---------------------------------------------------------------------------
#define WXS 0
#define WTS (128 * 68)
#define WWS (128 * 68 + 32 * 68)
#define SMEM_W ((128 * 68 + 32 * 68 + 392 * 32) * 4)

__global__ __launch_bounds__(256, 2) void kernW(
    const float* __restrict__ x,
    const float* __restrict__ c1w, const float* __restrict__ c1b,
    const float* __restrict__ bng, const float* __restrict__ bnb,
    const float* __restrict__ bnm, const float* __restrict__ bnv,
    const float* __restrict__ c2w, const float* __restrict__ c2b)
{
    extern __shared__ float smw[];
    float* xs = smw + WXS;
    float* ts = smw + WTS;
    float* ws = smw + WWS;

    const int bIdx = blockIdx.x / 49;
    const int pc   = blockIdx.x % 49;
    const int p0   = pc * 64;
    const int tid  = threadIdx.x;
    const float* xb = x + (size_t)bIdx * CC * HWP + p0;

    for (int t = tid; t < 128 * 16; t += 256) {
        int c = t >> 4, f = t & 15;
        *(float4*)&xs[c * 68 + f * 4] = *(const float4*)(xb + (size_t)c * HWP + f * 4);
    }
    for (int t = tid; t < 392 * 8; t += 256)
        *(float4*)&ws[t * 4] = *(const float4*)(c2w + t * 4);
    __syncthreads();

    const int pxg = tid & 15, px0 = pxg * 4;

    // conv1: 2 rows x 4 px
    {
        int r0 = (tid >> 4) * 2;
        float a0[4] = {0.f, 0.f, 0.f, 0.f};
        float a1[4] = {0.f, 0.f, 0.f, 0.f};
        const float* w0p = c1w + (size_t)r0 * 128;
        const float* w1p = w0p + 128;
        #pragma unroll 8
        for (int k4 = 0; k4 < 32; k4++) {
            float wa[4], wb[4];
            *(float4*)wa = *(const float4*)(w0p + k4 * 4);
            *(float4*)wb = *(const float4*)(w1p + k4 * 4);
            #pragma unroll
            for (int kk = 0; kk < 4; kk++) {
                float xv[4];
                *(float4*)xv = *(float4*)&xs[(k4 * 4 + kk) * 68 + px0];
                #pragma unroll
                for (int i = 0; i < 4; i++) {
                    a0[i] = fmaf(wa[kk], xv[i], a0[i]);
                    a1[i] = fmaf(wb[kk], xv[i], a1[i]);
                }
            }
        }
        #pragma unroll
        for (int rr = 0; rr < 2; rr++) {
            int r = r0 + rr;
            float sc = bng[r] * rsqrtf(bnv[r] + 1e-5f);
            float sh = (c1b[r] - bnm[r]) * sc + bnb[r];
            float* ap = rr ? a1 : a0;
            float4 o;
            o.x = fmaxf(fmaf(ap[0], sc, sh), 0.f);
            o.y = fmaxf(fmaf(ap[1], sc, sh), 0.f);
            o.z = fmaxf(fmaf(ap[2], sc, sh), 0.f);
            o.w = fmaxf(fmaf(ap[3], sc, sh), 0.f);
            *(float4*)&ts[r * 68 + px0] = o;
        }
    }
    __syncthreads();

    // conv2: 7 chunks of 64 oc, 4 oc x 4 px
    {
        const int og = tid >> 4;
        for (int ch = 0; ch < 7; ch++) {
            int ocb = ch * 64 + og * 4;
            float a[4][4];
            #pragma unroll
            for (int q = 0; q < 4; q++)
                #pragma unroll
                for (int i = 0; i < 4; i++) a[q][i] = 0.f;
            int oc0 = ocb < 388 ? ocb : 388;
            #pragma unroll
            for (int k4 = 0; k4 < 8; k4++) {
                float wv[4][4];
                #pragma unroll
                for (int q = 0; q < 4; q++)
                    *(float4*)wv[q] = *(float4*)&ws[(oc0 + q) * 32 + k4 * 4];
                #pragma unroll
                for (int kk = 0; kk < 4; kk++) {
                    float xv[4];
                    *(float4*)xv = *(float4*)&ts[(k4 * 4 + kk) * 68 + px0];
                    #pragma unroll
                    for (int q = 0; q < 4; q++)
                        #pragma unroll
                        for (int i = 0; i < 4; i++)
                            a[q][i] = fmaf(wv[q][kk], xv[i], a[q][i]);
                }
            }
            #pragma unroll
            for (int q = 0; q < 4; q++) {
                int oc = oc0 + q;
                if (ocb + q < 392) {
                    float bb = c2b[oc];
                    float4 o = {a[q][0] + bb, a[q][1] + bb, a[q][2] + bb, a[q][3] + bb};
                    *(float4*)(g_wgt + ((size_t)bIdx * OCH + oc) * HWP + p0 + px0) = o;
                }
            }
        }
    }
}

// ---------------------------------------------------------------------------
// kernI: involution per (b,h)
// ---------------------------------------------------------------------------
__global__ __launch_bounds__(256) void kernI(const float* __restrict__ x)
{
    __shared__ float hs_[16 * 7 * 62];
    __shared__ float ws_[49 * 57];

    const int bIdx = blockIdx.x / 56;
    const int h    = blockIdx.x % 56;
    const int tid  = threadIdx.x;
    const float* xb = x + (size_t)bIdx * CC * HWP;

    for (int g = 0; g < 8; g++) {
        for (int t = tid; t < 49 * 56; t += 256) {
            int k = t / 56, w = t % 56;
            ws_[k * 57 + w] = g_wgt[((size_t)bIdx * OCH + g * 49 + k) * HWP + h * 56 + w];
        }
        for (int t = tid; t < 16 * 7 * 62; t += 256) {
            int wq = t % 62, rr = (t / 62) % 7, c2 = t / 434;
            int h2 = h + rr - 3, w2 = wq - 3;
            float v = 0.f;
            if ((unsigned)h2 < 56u && (unsigned)w2 < 56u)
                v = xb[(size_t)(g * 16 + c2) * HWP + h2 * 56 + w2];
            hs_[t] = v;
        }
        __syncthreads();

        if (tid < 224) {
            const int wq = tid % 28, cq = tid / 28;
            const int w0 = wq * 2, c0 = cq * 2;
            float acc[2][2] = {{0.f, 0.f}, {0.f, 0.f}};
            #pragma unroll
            for (int kh = 0; kh < 7; kh++) {
                float wv0[7], wv1[7];
                #pragma unroll
                for (int kw = 0; kw < 7; kw++) {
                    wv0[kw] = ws_[(kh * 7 + kw) * 57 + w0];
                    wv1[kw] = ws_[(kh * 7 + kw) * 57 + w0 + 1];
                }
                #pragma unroll
                for (int cc2 = 0; cc2 < 2; cc2++) {
                    const float* xr = &hs_[(c0 + cc2) * 434 + kh * 62 + w0];
                    float xw[8];
                    #pragma unroll
                    for (int i = 0; i < 4; i++)
                        *(float2*)&xw[i * 2] = *(const float2*)(xr + i * 2);
                    #pragma unroll
                    for (int kw = 0; kw < 7; kw++) {
                        acc[0][cc2] = fmaf(wv0[kw], xw[kw],     acc[0][cc2]);
                        acc[1][cc2] = fmaf(wv1[kw], xw[kw + 1], acc[1][cc2]);
                    }
                }
            }
            size_t pxb = (size_t)bIdx * HWP + (size_t)h * 56;
            int cbase = g * 16 + c0;
            *(float2*)(g_inv + (pxb + w0)     * CC + cbase) = make_float2(acc[0][0], acc[0][1]);
            *(float2*)(g_inv + (pxb + w0 + 1) * CC + cbase) = make_float2(acc[1][0], acc[1][1]);
        }
        __syncthreads();
    }
}

// ---------------------------------------------------------------------------
// kernM v3: LN + MLP. 128-px CTA, 8 warps = 4 rowgroups x 2 colgroups.
// B operands via LDG of pre-permuted fragments; hs exchanged via smem.
// smem: b1s 2048B @0, b2s 512B @2048, ysH @2560 (128x272), ysL, hsH (128x144), hsL
// ---------------------------------------------------------------------------
#define MS_B1  0
#define MS_B2  2048
#define MS_YSH 2560
#define MS_YSL (MS_YSH + 34816)
#define MS_HSH (MS_YSL + 34816)
#define MS_HSL (MS_HSH + 18432)
#define SMEM_M (MS_HSL + 18432)

__global__ __launch_bounds__(256, 2) void kernM(
    const float* __restrict__ x,
    const float* __restrict__ b1, const float* __restrict__ b2,
    const float* __restrict__ lnw, const float* __restrict__ lnb,
    float* __restrict__ out)
{
    extern __shared__ char smraw[];
    const uint32_t sb = smem_to_u32(smraw);
    float* b1s = (float*)(smraw + MS_B1);
    float* b2s = (float*)(smraw + MS_B2);

    const int tid = threadIdx.x;
    const int wid = tid >> 5;
    const int l   = tid & 31;
    const size_t p0 = (size_t)blockIdx.x * 128;

    for (int t = tid; t < 512; t += 256) b1s[t] = b1[t];
    if (tid < 128) b2s[tid] = b2[tid];

    // ---- LN + bf16 hi/lo staging of ys ----
    {
        const int px = tid >> 1, half = tid & 1;
        const float* src = g_inv + (p0 + px) * CC + half * 64;
        float s = 0.f, s2 = 0.f;
        #pragma unroll 4
        for (int i = 0; i < 64; i += 4) {
            float4 v = *(const float4*)(src + i);
            s += v.x + v.y + v.z + v.w;
            s2 = fmaf(v.x, v.x, s2); s2 = fmaf(v.y, v.y, s2);
            s2 = fmaf(v.z, v.z, s2); s2 = fmaf(v.w, v.w, s2);
        }
        s  += __shfl_xor_sync(0xffffffffu, s, 1);
        s2 += __shfl_xor_sync(0xffffffffu, s2, 1);
        float mu  = s * (1.f / 128.f);
        float var = s2 * (1.f / 128.f) - mu * mu;
        float rs  = rsqrtf(var + 1e-6f);
        #pragma unroll 4
        for (int i = 0; i < 64; i += 2) {
            int k = half * 64 + i;
            float y0 = (src[i]     - mu) * rs * lnw[k]     + lnb[k];
            float y1 = (src[i + 1] - mu) * rs * lnw[k + 1] + lnb[k + 1];
            uint32_t hi, lo;
            split_pack(y0, y1, hi, lo);
            *(uint32_t*)(smraw + MS_YSH + px * 272 + k * 2) = hi;
            *(uint32_t*)(smraw + MS_YSL + px * 272 + k * 2) = lo;
        }
    }
    __syncthreads();

    const int rg = wid >> 1;          // row-group: rows rg*32..+32
    const int cg = wid & 1;           // col-group
    const int r_l   = l & 15;
    const int koffB = (l >> 4) * 16;  // byte offset selecting k-half for ldsm

    // ys ldsm bases for the two 16-row m-tiles
    uint32_t aBH[2], aBL[2];
    #pragma unroll
    for (int mt = 0; mt < 2; mt++) {
        uint32_t ro = (rg * 32 + mt * 16 + r_l) * 272 + koffB;
        aBH[mt] = sb + MS_YSH + ro;
        aBL[mt] = sb + MS_YSL + ro;
    }
    // hs ldsm bases
    uint32_t hBH[2], hBL[2];
    #pragma unroll
    for (int mt = 0; mt < 2; mt++) {
        uint32_t ro = (rg * 32 + mt * 16 + r_l) * 144 + koffB;
        hBH[mt] = sb + MS_HSH + ro;
        hBL[mt] = sb + MS_HSL + ro;
    }

    float acc2[16][4];
    #pragma unroll
    for (int n = 0; n < 16; n++)
        #pragma unroll
        for (int q = 0; q < 4; q++) acc2[n][q] = 0.f;

    const uint4* w1p = g_w1f + l;
    const uint4* w2p = g_w2f + l;

    for (int nb = 0; nb < 8; nb++) {
        const int j0 = nb * 64;

        // ---- GEMM1: c1[32 rows x 32 cols] = ys @ w1^T (3-pass split) ----
        float c1[8][4];
        #pragma unroll
        for (int n = 0; n < 8; n++)
            #pragma unroll
            for (int q = 0; q < 4; q++) c1[n][q] = 0.f;

        #pragma unroll
        for (int kt = 0; kt < 8; kt++) {
            uint32_t ah0[4], ah1[4], al0[4], al1[4];
            ldsm4(ah0, aBH[0] + kt * 32);
            ldsm4(ah1, aBH[1] + kt * 32);
            ldsm4(al0, aBL[0] + kt * 32);
            ldsm4(al1, aBL[1] + kt * 32);
            #pragma unroll
            for (int nt = 0; nt < 4; nt++) {
                uint4 w = w1p[(size_t)(((nb * 8 + kt) * 8) + cg * 4 + nt) * 32];
                mma16816(c1[nt],     ah0, w.x, w.y);
                mma16816(c1[nt],     ah0, w.z, w.w);
                mma16816(c1[nt],     al0, w.x, w.y);
                mma16816(c1[4 + nt], ah1, w.x, w.y);
                mma16816(c1[4 + nt], ah1, w.z, w.w);
                mma16816(c1[4 + nt], al1, w.x, w.y);
            }
        }

        // ---- bias + exact GELU -> hs (hi/lo bf16) ----
        #pragma unroll
        for (int mt = 0; mt < 2; mt++) {
            int row = rg * 32 + mt * 16 + (l >> 2);
            #pragma unroll
            for (int nt = 0; nt < 4; nt++) {
                int jc = cg * 32 + nt * 8 + (l & 3) * 2;   // chunk-local col
                float2 bv = *(const float2*)&b1s[j0 + jc];
                float v0 = c1[mt * 4 + nt][0] + bv.x;
                float v1 = c1[mt * 4 + nt][1] + bv.y;
                float v2 = c1[mt * 4 + nt][2] + bv.x;
                float v3 = c1[mt * 4 + nt][3] + bv.y;
                float g0 = 0.5f * v0 * (1.f + erff(v0 * 0.70710678118654752f));
                float g1 = 0.5f * v1 * (1.f + erff(v1 * 0.70710678118654752f));
                float g2 = 0.5f * v2 * (1.f + erff(v2 * 0.70710678118654752f));
                float g3 = 0.5f * v3 * (1.f + erff(v3 * 0.70710678118654752f));
                uint32_t hi, lo;
                split_pack(g0, g1, hi, lo);
                *(uint32_t*)(smraw + MS_HSH + row * 144 + jc * 2) = hi;
                *(uint32_t*)(smraw + MS_HSL + row * 144 + jc * 2) = lo;
                split_pack(g2, g3, hi, lo);
                *(uint32_t*)(smraw + MS_HSH + (row + 8) * 144 + jc * 2) = hi;
                *(uint32_t*)(smraw + MS_HSL + (row + 8) * 144 + jc * 2) = lo;
            }
        }
        __syncthreads();

        // ---- GEMM2: acc2[32 rows x 64 cols] += hs @ w2^T (3-pass split) ----
        #pragma unroll
        for (int kt2 = 0; kt2 < 4; kt2++) {
            uint32_t a0h[4], a1h[4], a0l[4], a1l[4];
            ldsm4(a0h, hBH[0] + kt2 * 32);
            ldsm4(a1h, hBH[1] + kt2 * 32);
            ldsm4(a0l, hBL[0] + kt2 * 32);
            ldsm4(a1l, hBL[1] + kt2 * 32);
            #pragma unroll
            for (int nt = 0; nt < 8; nt++) {
                uint4 w = w2p[(size_t)(((nb * 4 + kt2) * 16) + cg * 8 + nt) * 32];
                mma16816(acc2[nt],     a0h, w.x, w.y);
                mma16816(acc2[nt],     a0h, w.z, w.w);
                mma16816(acc2[nt],     a0l, w.x, w.y);
                mma16816(acc2[8 + nt], a1h, w.x, w.y);
                mma16816(acc2[8 + nt], a1h, w.z, w.w);
                mma16816(acc2[8 + nt], a1l, w.x, w.y);
            }
        }
        __syncthreads();
    }

    // ---- epilogue: + b2 + x, NCHW store ----
    #pragma unroll
    for (int mt = 0; mt < 2; mt++) {
        #pragma unroll
        for (int half = 0; half < 2; half++) {
            int row = rg * 32 + mt * 16 + (l >> 2) + half * 8;
            size_t gpx = p0 + row;
            size_t bI = gpx / HWP, hw = gpx % HWP;
            const float* xb = x + bI * CC * HWP + hw;
            float* ob = out + bI * CC * HWP + hw;
            #pragma unroll
            for (int nt = 0; nt < 8; nt++) {
                int c = cg * 64 + nt * 8 + (l & 3) * 2;
                ob[(size_t)c * HWP] =
                    acc2[mt * 8 + nt][half * 2] + b2s[c] + xb[(size_t)c * HWP];
                ob[(size_t)(c + 1) * HWP] =
                    acc2[mt * 8 + nt][half * 2 + 1] + b2s[c + 1] + xb[(size_t)(c + 1) * HWP];
            }
        }
    }
}

// ---------------------------------------------------------------------------
extern "C" void kernel_launch(void* const* d_in, const int* in_sizes, int n_in,
                              void* d_out, int out_size)
{
    const float* x   = (const float*)d_in[0];
    const float* c1w = (const float*)d_in[1];
    const float* c1b = (const float*)d_in[2];
    const float* bng = (const float*)d_in[3];
    const float* bnb = (const float*)d_in[4];
    const float* bnm = (const float*)d_in[5];
    const float* bnv = (const float*)d_in[6];
    const float* c2w = (const float*)d_in[7];
    const float* c2b = (const float*)d_in[8];
    const float* lnw = (const float*)d_in[9];
    const float* lnb = (const float*)d_in[10];
    const float* w1  = (const float*)d_in[11];
    const float* b1  = (const float*)d_in[12];
    const float* w2  = (const float*)d_in[13];
    const float* b2  = (const float*)d_in[14];
    float* out = (float*)d_out;

    cudaFuncSetAttribute(kernW, cudaFuncAttributeMaxDynamicSharedMemorySize, SMEM_W);
    cudaFuncSetAttribute(kernM, cudaFuncAttributeMaxDynamicSharedMemorySize, SMEM_M);

    kernP<<<128, 256>>>(w1, w2);
    kernW<<<BB * 49, 256, SMEM_W>>>(x, c1w, c1b, bng, bnb, bnm, bnv, c2w, c2b);
    kernI<<<BB * HH, 256>>>(x);
    kernM<<<NPIX / 128, 256, SMEM_M>>>(x, b1, b2, lnw, lnb, out);
}

// round 9
// speedup vs baseline: 2.0469x; 1.0437x over previous
#include <cuda_runtime.h>
#include <cuda_bf16.h>
#include <math.h>
#include <stdint.h>

#define BB   8
#define CC   128
#define HH   56
#define WW   56
#define HWP  3136
#define REDC 32
#define GRP  8
#define KK   49
#define OCH  392
#define HID  512
#define NPIX 25088

// scratch
__device__ float g_wgt[(size_t)BB * OCH * HWP];
__device__ float g_inv[(size_t)NPIX * CC];
// weights pre-permuted into mma B-fragment layout
__device__ uint4 g_w1f[8 * 8 * 8 * 32];
__device__ uint4 g_w2f[8 * 4 * 16 * 32];

// ======================== helpers ========================
__device__ __forceinline__ uint32_t smem_to_u32(const void* p) {
    uint32_t a;
    asm("{ .reg .u64 t; cvta.to.shared.u64 t, %1; cvt.u32.u64 %0, t; }"
        : "=r"(a) : "l"(p));
    return a;
}
__device__ __forceinline__ void ldsm4(uint32_t r[4], uint32_t addr) {
    asm volatile("ldmatrix.sync.aligned.m8n8.x4.shared.b16 {%0,%1,%2,%3}, [%4];"
        : "=r"(r[0]), "=r"(r[1]), "=r"(r[2]), "=r"(r[3]) : "r"(addr));
}
__device__ __forceinline__ void mma16816(float c[4], const uint32_t a[4],
                                         uint32_t b0, uint32_t b1) {
    asm volatile(
        "mma.sync.aligned.m16n8k16.row.col.f32.bf16.bf16.f32 "
        "{%0,%1,%2,%3}, {%4,%5,%6,%7}, {%8,%9}, {%0,%1,%2,%3};"
        : "+f"(c[0]), "+f"(c[1]), "+f"(c[2]), "+f"(c[3])
        : "r"(a[0]), "r"(a[1]), "r"(a[2]), "r"(a[3]), "r"(b0), "r"(b1));
}
__device__ __forceinline__ void split_pack(float v0, float v1, uint32_t& hi, uint32_t& lo) {
    __nv_bfloat16 h0 = __float2bfloat16(v0);
    __nv_bfloat16 h1 = __float2bfloat16(v1);
    __nv_bfloat16 l0 = __float2bfloat16(v0 - __bfloat162float(h0));
    __nv_bfloat16 l1 = __float2bfloat16(v1 - __bfloat162float(h1));
    __nv_bfloat162 hp; hp.x = h0; hp.y = h1;
    __nv_bfloat162 lp; lp.x = l0; lp.y = l1;
    hi = *(uint32_t*)&hp; lo = *(uint32_t*)&lp;
}

// ---------------------------------------------------------------------------
// kernP: permute w1/w2 into bf16 hi/lo mma fragments
// ---------------------------------------------------------------------------
__global__ __launch_bounds__(256) void kernP(const float* __restrict__ w1,
                                             const float* __restrict__ w2)
{
    int idx = blockIdx.x * 256 + threadIdx.x;   // [0, 32768)
    float v00, v01, v10, v11;
    uint4* dst;
    if (idx < 16384) {
        int l  = idx & 31;
        int nt = (idx >> 5) & 7;
        int kt = (idx >> 8) & 7;
        int c  = idx >> 11;
        int n = c * 64 + nt * 8 + (l >> 2);
        int k = kt * 16 + (l & 3) * 2;
        const float* p = w1 + (size_t)n * 128 + k;
        v00 = p[0]; v01 = p[1]; v10 = p[8]; v11 = p[9];
        dst = g_w1f + idx;
    } else {
        int i2 = idx - 16384;
        int l   = i2 & 31;
        int nt  = (i2 >> 5) & 15;
        int kt2 = (i2 >> 9) & 3;
        int nb  = i2 >> 11;
        int n = nt * 8 + (l >> 2);
        int k = nb * 64 + kt2 * 16 + (l & 3) * 2;
        const float* p = w2 + (size_t)n * 512 + k;
        v00 = p[0]; v01 = p[1]; v10 = p[8]; v11 = p[9];
        dst = g_w2f + i2;
    }
    uint32_t h0, l0, h1, l1;
    split_pack(v00, v01, h0, l0);
    split_pack(v10, v11, h1, l1);
    *dst = make_uint4(h0, h1, l0, l1);
}

// ---------------------------------------------------------------------------
// kernW: conv1(128->32)+BN+ReLU then conv2(32->392)
// ---------------------------------------------------------------------------
#define WXS 0
#define WTS (128 * 68)
#define WWS (128 * 68 + 32 * 68)
#define SMEM_W ((128 * 68 + 32 * 68 + 392 * 32) * 4)

__global__ __launch_bounds__(256, 2) void kernW(
    const float* __restrict__ x,
    const float* __restrict__ c1w, const float* __restrict__ c1b,
    const float* __restrict__ bng, const float* __restrict__ bnb,
    const float* __restrict__ bnm, const float* __restrict__ bnv,
    const float* __restrict__ c2w, const float* __restrict__ c2b)
{
    extern __shared__ float smw[];
    float* xs = smw + WXS;
    float* ts = smw + WTS;
    float* ws = smw + WWS;

    const int bIdx = blockIdx.x / 49;
    const int pc   = blockIdx.x % 49;
    const int p0   = pc * 64;
    const int tid  = threadIdx.x;
    const float* xb = x + (size_t)bIdx * CC * HWP + p0;

    for (int t = tid; t < 128 * 16; t += 256) {
        int c = t >> 4, f = t & 15;
        *(float4*)&xs[c * 68 + f * 4] = *(const float4*)(xb + (size_t)c * HWP + f * 4);
    }
    for (int t = tid; t < 392 * 8; t += 256)
        *(float4*)&ws[t * 4] = *(const float4*)(c2w + t * 4);
    __syncthreads();

    const int pxg = tid & 15, px0 = pxg * 4;

    {
        int r0 = (tid >> 4) * 2;
        float a0[4] = {0.f, 0.f, 0.f, 0.f};
        float a1[4] = {0.f, 0.f, 0.f, 0.f};
        const float* w0p = c1w + (size_t)r0 * 128;
        const float* w1p = w0p + 128;
        #pragma unroll 8
        for (int k4 = 0; k4 < 32; k4++) {
            float wa[4], wb[4];
            *(float4*)wa = *(const float4*)(w0p + k4 * 4);
            *(float4*)wb = *(const float4*)(w1p + k4 * 4);
            #pragma unroll
            for (int kk = 0; kk < 4; kk++) {
                float xv[4];
                *(float4*)xv = *(float4*)&xs[(k4 * 4 + kk) * 68 + px0];
                #pragma unroll
                for (int i = 0; i < 4; i++) {
                    a0[i] = fmaf(wa[kk], xv[i], a0[i]);
                    a1[i] = fmaf(wb[kk], xv[i], a1[i]);
                }
            }
        }
        #pragma unroll
        for (int rr = 0; rr < 2; rr++) {
            int r = r0 + rr;
            float sc = bng[r] * rsqrtf(bnv[r] + 1e-5f);
            float sh = (c1b[r] - bnm[r]) * sc + bnb[r];
            float* ap = rr ? a1 : a0;
            float4 o;
            o.x = fmaxf(fmaf(ap[0], sc, sh), 0.f);
            o.y = fmaxf(fmaf(ap[1], sc, sh), 0.f);
            o.z = fmaxf(fmaf(ap[2], sc, sh), 0.f);
            o.w = fmaxf(fmaf(ap[3], sc, sh), 0.f);
            *(float4*)&ts[r * 68 + px0] = o;
        }
    }
    __syncthreads();

    {
        const int og = tid >> 4;
        for (int ch = 0; ch < 7; ch++) {
            int ocb = ch * 64 + og * 4;
            float a[4][4];
            #pragma unroll
            for (int q = 0; q < 4; q++)
                #pragma unroll
                for (int i = 0; i < 4; i++) a[q][i] = 0.f;
            int oc0 = ocb < 388 ? ocb : 388;
            #pragma unroll
            for (int k4 = 0; k4 < 8; k4++) {
                float wv[4][4];
                #pragma unroll
                for (int q = 0; q < 4; q++)
                    *(float4*)wv[q] = *(float4*)&ws[(oc0 + q) * 32 + k4 * 4];
                #pragma unroll
                for (int kk = 0; kk < 4; kk++) {
                    float xv[4];
                    *(float4*)xv = *(float4*)&ts[(k4 * 4 + kk) * 68 + px0];
                    #pragma unroll
                    for (int q = 0; q < 4; q++)
                        #pragma unroll
                        for (int i = 0; i < 4; i++)
                            a[q][i] = fmaf(wv[q][kk], xv[i], a[q][i]);
                }
            }
            #pragma unroll
            for (int q = 0; q < 4; q++) {
                int oc = oc0 + q;
                if (ocb + q < 392) {
                    float bb = c2b[oc];
                    float4 o = {a[q][0] + bb, a[q][1] + bb, a[q][2] + bb, a[q][3] + bb};
                    *(float4*)(g_wgt + ((size_t)bIdx * OCH + oc) * HWP + p0 + px0) = o;
                }
            }
        }
    }
}

// ---------------------------------------------------------------------------
// kernI v2: involution per (b, h-pair). 224 thr = 14 wq x 8 cslot x 2 rows.
// Thread computes 4w x 4ch via float4 loads. 4 iters of 32 channels.
// smem: halo [32ch][8r][64] pitch 516/ch ; wsm [4 planes][49*56]
// ---------------------------------------------------------------------------
#define IH_PITCH 516
#define IW_SZ    2744
#define ISM_WS   (32 * IH_PITCH)
#define SMEM_I   ((32 * IH_PITCH + 4 * IW_SZ) * 4)

__global__ __launch_bounds__(224, 2) void kernI(const float* __restrict__ x)
{
    extern __shared__ float smi[];
    float* halo = smi;
    float* wsm  = smi + ISM_WS;

    const int bIdx = blockIdx.x / 28;
    const int hp   = blockIdx.x % 28;
    const int h0   = hp * 2;
    const int tid  = threadIdx.x;
    const float* xb = x + (size_t)bIdx * CC * HWP;

    const int wq    = tid % 14;
    const int s2    = tid / 14;     // 0..15
    const int cslot = s2 & 7;
    const int hr    = s2 >> 3;
    const int w0    = wq * 4;
    const int gl    = cslot >> 2;

    for (int it = 0; it < 4; it++) {
        const int cbase = it * 32;
        if (it) __syncthreads();

        // stage weights: 4 planes = (hr2, gl2)
        for (int t = tid; t < 4 * IW_SZ; t += 224) {
            int pl = t / IW_SZ;
            int r  = t - pl * IW_SZ;
            int hr2 = pl >> 1, gl2 = pl & 1;
            int k = r / 56, w = r - k * 56;
            wsm[t] = g_wgt[((size_t)bIdx * OCH + (it * 2 + gl2) * KK + k) * HWP
                           + (h0 + hr2) * 56 + w];
        }
        // stage halo: 32 ch x 8 rows x 64 cols (zero-padded)
        for (int t = tid; t < 32 * 8 * 64; t += 224) {
            int j  = t & 63;
            int r  = (t >> 6) & 7;
            int cl = t >> 9;
            int h2 = h0 + r - 3, w2 = j - 3;
            float v = 0.f;
            if ((unsigned)h2 < 56u && (unsigned)w2 < 56u)
                v = xb[(size_t)(cbase + cl) * HWP + h2 * 56 + w2];
            halo[cl * IH_PITCH + r * 64 + j] = v;
        }
        __syncthreads();

        float acc[4][4];
        #pragma unroll
        for (int wi = 0; wi < 4; wi++)
            #pragma unroll
            for (int c = 0; c < 4; c++) acc[wi][c] = 0.f;

        const float* hb = halo + (cslot * 4) * IH_PITCH + hr * 64 + w0;
        const float* wb = wsm + (hr * 2 + gl) * IW_SZ + w0;

        #pragma unroll
        for (int kh = 0; kh < 7; kh++) {
            float xr[4][12];
            #pragma unroll
            for (int c = 0; c < 4; c++) {
                const float* hq = hb + c * IH_PITCH + kh * 64;
                *(float4*)&xr[c][0] = *(const float4*)hq;
                *(float4*)&xr[c][4] = *(const float4*)(hq + 4);
                *(float4*)&xr[c][8] = *(const float4*)(hq + 8);
            }
            #pragma unroll
            for (int kw = 0; kw < 7; kw++) {
                float4 wv = *(const float4*)(wb + (kh * 7 + kw) * 56);
                #pragma unroll
                for (int c = 0; c < 4; c++) {
                    acc[0][c] = fmaf(wv.x, xr[c][kw],     acc[0][c]);
                    acc[1][c] = fmaf(wv.y, xr[c][kw + 1], acc[1][c]);
                    acc[2][c] = fmaf(wv.z, xr[c][kw + 2], acc[2][c]);
                    acc[3][c] = fmaf(wv.w, xr[c][kw + 3], acc[3][c]);
                }
            }
        }

        size_t pxb = (size_t)bIdx * HWP + (size_t)(h0 + hr) * 56;
        #pragma unroll
        for (int wi = 0; wi < 4; wi++)
            *(float4*)(g_inv + (pxb + w0 + wi) * CC + cbase + cslot * 4) =
                make_float4(acc[wi][0], acc[wi][1], acc[wi][2], acc[wi][3]);
    }
}

// ---------------------------------------------------------------------------
// kernM: LN + MLP, mma.sync bf16 split. Named barriers per rowgroup pair.
// ---------------------------------------------------------------------------
#define MS_B1  0
#define MS_B2  2048
#define MS_YSH 2560
#define MS_YSL (MS_YSH + 34816)
#define MS_HSH (MS_YSL + 34816)
#define MS_HSL (MS_HSH + 18432)
#define SMEM_M (MS_HSL + 18432)

#define BARX(id) asm volatile("bar.sync %0, 64;" :: "r"(id) : "memory")

__global__ __launch_bounds__(256, 2) void kernM(
    const float* __restrict__ x,
    const float* __restrict__ b1, const float* __restrict__ b2,
    const float* __restrict__ lnw, const float* __restrict__ lnb,
    float* __restrict__ out)
{
    extern __shared__ char smraw[];
    const uint32_t sb = smem_to_u32(smraw);
    float* b1s = (float*)(smraw + MS_B1);
    float* b2s = (float*)(smraw + MS_B2);

    const int tid = threadIdx.x;
    const int wid = tid >> 5;
    const int l   = tid & 31;
    const size_t p0 = (size_t)blockIdx.x * 128;

    for (int t = tid; t < 512; t += 256) b1s[t] = b1[t];
    if (tid < 128) b2s[tid] = b2[tid];

    // ---- LN + bf16 hi/lo staging of ys ----
    {
        const int px = tid >> 1, half = tid & 1;
        const float* src = g_inv + (p0 + px) * CC + half * 64;
        float s = 0.f, s2 = 0.f;
        #pragma unroll 4
        for (int i = 0; i < 64; i += 4) {
            float4 v = *(const float4*)(src + i);
            s += v.x + v.y + v.z + v.w;
            s2 = fmaf(v.x, v.x, s2); s2 = fmaf(v.y, v.y, s2);
            s2 = fmaf(v.z, v.z, s2); s2 = fmaf(v.w, v.w, s2);
        }
        s  += __shfl_xor_sync(0xffffffffu, s, 1);
        s2 += __shfl_xor_sync(0xffffffffu, s2, 1);
        float mu  = s * (1.f / 128.f);
        float var = s2 * (1.f / 128.f) - mu * mu;
        float rs  = rsqrtf(var + 1e-6f);
        #pragma unroll 4
        for (int i = 0; i < 64; i += 2) {
            int k = half * 64 + i;
            float y0 = (src[i]     - mu) * rs * lnw[k]     + lnb[k];
            float y1 = (src[i + 1] - mu) * rs * lnw[k + 1] + lnb[k + 1];
            uint32_t hi, lo;
            split_pack(y0, y1, hi, lo);
            *(uint32_t*)(smraw + MS_YSH + px * 272 + k * 2) = hi;
            *(uint32_t*)(smraw + MS_YSL + px * 272 + k * 2) = lo;
        }
    }
    __syncthreads();

    const int rg = wid >> 1;
    const int cg = wid & 1;
    const int r_l   = l & 15;
    const int koffB = (l >> 4) * 16;
    const int barid = 8 + rg;

    uint32_t aBH[2], aBL[2];
    #pragma unroll
    for (int mt = 0; mt < 2; mt++) {
        uint32_t ro = (rg * 32 + mt * 16 + r_l) * 272 + koffB;
        aBH[mt] = sb + MS_YSH + ro;
        aBL[mt] = sb + MS_YSL + ro;
    }
    uint32_t hBH[2], hBL[2];
    #pragma unroll
    for (int mt = 0; mt < 2; mt++) {
        uint32_t ro = (rg * 32 + mt * 16 + r_l) * 144 + koffB;
        hBH[mt] = sb + MS_HSH + ro;
        hBL[mt] = sb + MS_HSL + ro;
    }

    float acc2[16][4];
    #pragma unroll
    for (int n = 0; n < 16; n++)
        #pragma unroll
        for (int q = 0; q < 4; q++) acc2[n][q] = 0.f;

    const uint4* w1p = g_w1f + l;
    const uint4* w2p = g_w2f + l;

    for (int nb = 0; nb < 8; nb++) {
        const int j0 = nb * 64;

        // ---- GEMM1 ----
        float c1[8][4];
        #pragma unroll
        for (int n = 0; n < 8; n++)
            #pragma unroll
            for (int q = 0; q < 4; q++) c1[n][q] = 0.f;

        #pragma unroll
        for (int kt = 0; kt < 8; kt++) {
            uint32_t ah0[4], ah1[4], al0[4], al1[4];
            ldsm4(ah0, aBH[0] + kt * 32);
            ldsm4(ah1, aBH[1] + kt * 32);
            ldsm4(al0, aBL[0] + kt * 32);
            ldsm4(al1, aBL[1] + kt * 32);
            #pragma unroll
            for (int nt = 0; nt < 4; nt++) {
                uint4 w = w1p[(size_t)(((nb * 8 + kt) * 8) + cg * 4 + nt) * 32];
                mma16816(c1[nt],     ah0, w.x, w.y);
                mma16816(c1[nt],     ah0, w.z, w.w);
                mma16816(c1[nt],     al0, w.x, w.y);
                mma16816(c1[4 + nt], ah1, w.x, w.y);
                mma16816(c1[4 + nt], ah1, w.z, w.w);
                mma16816(c1[4 + nt], al1, w.x, w.y);
            }
        }

        // ---- bias + exact GELU -> hs ----
        #pragma unroll
        for (int mt = 0; mt < 2; mt++) {
            int row = rg * 32 + mt * 16 + (l >> 2);
            #pragma unroll
            for (int nt = 0; nt < 4; nt++) {
                int jc = cg * 32 + nt * 8 + (l & 3) * 2;
                float2 bv = *(const float2*)&b1s[j0 + jc];
                float v0 = c1[mt * 4 + nt][0] + bv.x;
                float v1 = c1[mt * 4 + nt][1] + bv.y;
                float v2 = c1[mt * 4 + nt][2] + bv.x;
                float v3 = c1[mt * 4 + nt][3] + bv.y;
                float g0 = 0.5f * v0 * (1.f + erff(v0 * 0.70710678118654752f));
                float g1 = 0.5f * v1 * (1.f + erff(v1 * 0.70710678118654752f));
                float g2 = 0.5f * v2 * (1.f + erff(v2 * 0.70710678118654752f));
                float g3 = 0.5f * v3 * (1.f + erff(v3 * 0.70710678118654752f));
                uint32_t hi, lo;
                split_pack(g0, g1, hi, lo);
                *(uint32_t*)(smraw + MS_HSH + row * 144 + jc * 2) = hi;
                *(uint32_t*)(smraw + MS_HSL + row * 144 + jc * 2) = lo;
                split_pack(g2, g3, hi, lo);
                *(uint32_t*)(smraw + MS_HSH + (row + 8) * 144 + jc * 2) = hi;
                *(uint32_t*)(smraw + MS_HSL + (row + 8) * 144 + jc * 2) = lo;
            }
        }
        BARX(barid);

        // ---- GEMM2 ----
        #pragma unroll
        for (int kt2 = 0; kt2 < 4; kt2++) {
            uint32_t a0h[4], a1h[4], a0l[4], a1l[4];
            ldsm4(a0h, hBH[0] + kt2 * 32);
            ldsm4(a1h, hBH[1] + kt2 * 32);
            ldsm4(a0l, hBL[0] + kt2 * 32);
            ldsm4(a1l, hBL[1] + kt2 * 32);
            #pragma unroll
            for (int nt = 0; nt < 8; nt++) {
                uint4 w = w2p[(size_t)(((nb * 4 + kt2) * 16) + cg * 8 + nt) * 32];
                mma16816(acc2[nt],     a0h, w.x, w.y);
                mma16816(acc2[nt],     a0h, w.z, w.w);
                mma16816(acc2[nt],     a0l, w.x, w.y);
                mma16816(acc2[8 + nt], a1h, w.x, w.y);
                mma16816(acc2[8 + nt], a1h, w.z, w.w);
                mma16816(acc2[8 + nt], a1l, w.x, w.y);
            }
        }
        BARX(barid);
    }

    // ---- epilogue ----
    #pragma unroll
    for (int mt = 0; mt < 2; mt++) {
        #pragma unroll
        for (int half = 0; half < 2; half++) {
            int row = rg * 32 + mt * 16 + (l >> 2) + half * 8;
            size_t gpx = p0 + row;
            size_t bI = gpx / HWP, hw = gpx % HWP;
            const float* xb = x + bI * CC * HWP + hw;
            float* ob = out + bI * CC * HWP + hw;
            #pragma unroll
            for (int nt = 0; nt < 8; nt++) {
                int c = cg * 64 + nt * 8 + (l & 3) * 2;
                ob[(size_t)c * HWP] =
                    acc2[mt * 8 + nt][half * 2] + b2s[c] + xb[(size_t)c * HWP];
                ob[(size_t)(c + 1) * HWP] =
                    acc2[mt * 8 + nt][half * 2 + 1] + b2s[c + 1] + xb[(size_t)(c + 1) * HWP];
            }
        }
    }
}

// ---------------------------------------------------------------------------
extern "C" void kernel_launch(void* const* d_in, const int* in_sizes, int n_in,
                              void* d_out, int out_size)
{
    const float* x   = (const float*)d_in[0];
    const float* c1w = (const float*)d_in[1];
    const float* c1b = (const float*)d_in[2];
    const float* bng = (const float*)d_in[3];
    const float* bnb = (const float*)d_in[4];
    const float* bnm = (const float*)d_in[5];
    const float* bnv = (const float*)d_in[6];
    const float* c2w = (const float*)d_in[7];
    const float* c2b = (const float*)d_in[8];
    const float* lnw = (const float*)d_in[9];
    const float* lnb = (const float*)d_in[10];
    const float* w1  = (const float*)d_in[11];
    const float* b1  = (const float*)d_in[12];
    const float* w2  = (const float*)d_in[13];
    const float* b2  = (const float*)d_in[14];
    float* out = (float*)d_out;

    cudaFuncSetAttribute(kernW, cudaFuncAttributeMaxDynamicSharedMemorySize, SMEM_W);
    cudaFuncSetAttribute(kernI, cudaFuncAttributeMaxDynamicSharedMemorySize, SMEM_I);
    cudaFuncSetAttribute(kernM, cudaFuncAttributeMaxDynamicSharedMemorySize, SMEM_M);

    kernP<<<128, 256>>>(w1, w2);
    kernW<<<BB * 49, 256, SMEM_W>>>(x, c1w, c1b, bng, bnb, bnm, bnv, c2w, c2b);
    kernI<<<BB * 28, 224, SMEM_I>>>(x);
    kernM<<<NPIX / 128, 256, SMEM_M>>>(x, b1, b2, lnw, lnb, out);
}

// round 10
// speedup vs baseline: 2.2527x; 1.1005x over previous
#include <cuda_runtime.h>
#include <cuda_bf16.h>
#include <math.h>
#include <stdint.h>

#define BB   8
#define CC   128
#define HH   56
#define WW   56
#define HWP  3136
#define REDC 32
#define GRP  8
#define KK   49
#define OCH  392
#define HID  512
#define NPIX 25088

// scratch
__device__ float g_wgt[(size_t)BB * OCH * HWP];
__device__ float g_inv[(size_t)NPIX * CC];
// weights pre-permuted into mma B-fragment layout
__device__ uint4 g_w1f[8 * 8 * 8 * 32];
__device__ uint4 g_w2f[8 * 4 * 16 * 32];

// ======================== helpers ========================
__device__ __forceinline__ uint32_t smem_to_u32(const void* p) {
    uint32_t a;
    asm("{ .reg .u64 t; cvta.to.shared.u64 t, %1; cvt.u32.u64 %0, t; }"
        : "=r"(a) : "l"(p));
    return a;
}
__device__ __forceinline__ void ldsm4(uint32_t r[4], uint32_t addr) {
    asm volatile("ldmatrix.sync.aligned.m8n8.x4.shared.b16 {%0,%1,%2,%3}, [%4];"
        : "=r"(r[0]), "=r"(r[1]), "=r"(r[2]), "=r"(r[3]) : "r"(addr));
}
__device__ __forceinline__ void mma16816(float c[4], const uint32_t a[4],
                                         uint32_t b0, uint32_t b1) {
    asm volatile(
        "mma.sync.aligned.m16n8k16.row.col.f32.bf16.bf16.f32 "
        "{%0,%1,%2,%3}, {%4,%5,%6,%7}, {%8,%9}, {%0,%1,%2,%3};"
        : "+f"(c[0]), "+f"(c[1]), "+f"(c[2]), "+f"(c[3])
        : "r"(a[0]), "r"(a[1]), "r"(a[2]), "r"(a[3]), "r"(b0), "r"(b1));
}
__device__ __forceinline__ void split_pack(float v0, float v1, uint32_t& hi, uint32_t& lo) {
    __nv_bfloat16 h0 = __float2bfloat16(v0);
    __nv_bfloat16 h1 = __float2bfloat16(v1);
    __nv_bfloat16 l0 = __float2bfloat16(v0 - __bfloat162float(h0));
    __nv_bfloat16 l1 = __float2bfloat16(v1 - __bfloat162float(h1));
    __nv_bfloat162 hp; hp.x = h0; hp.y = h1;
    __nv_bfloat162 lp; lp.x = l0; lp.y = l1;
    hi = *(uint32_t*)&hp; lo = *(uint32_t*)&lp;
}

// ---------------------------------------------------------------------------
// kernP: permute w1/w2 into bf16 hi/lo mma fragments
// ---------------------------------------------------------------------------
__global__ __launch_bounds__(256) void kernP(const float* __restrict__ w1,
                                             const float* __restrict__ w2)
{
    int idx = blockIdx.x * 256 + threadIdx.x;   // [0, 32768)
    float v00, v01, v10, v11;
    uint4* dst;
    if (idx < 16384) {
        int l  = idx & 31;
        int nt = (idx >> 5) & 7;
        int kt = (idx >> 8) & 7;
        int c  = idx >> 11;
        int n = c * 64 + nt * 8 + (l >> 2);
        int k = kt * 16 + (l & 3) * 2;
        const float* p = w1 + (size_t)n * 128 + k;
        v00 = p[0]; v01 = p[1]; v10 = p[8]; v11 = p[9];
        dst = g_w1f + idx;
    } else {
        int i2 = idx - 16384;
        int l   = i2 & 31;
        int nt  = (i2 >> 5) & 15;
        int kt2 = (i2 >> 9) & 3;
        int nb  = i2 >> 11;
        int n = nt * 8 + (l >> 2);
        int k = nb * 64 + kt2 * 16 + (l & 3) * 2;
        const float* p = w2 + (size_t)n * 512 + k;
        v00 = p[0]; v01 = p[1]; v10 = p[8]; v11 = p[9];
        dst = g_w2f + i2;
    }
    uint32_t h0, l0, h1, l1;
    split_pack(v00, v01, h0, l0);
    split_pack(v10, v11, h1, l1);
    *dst = make_uint4(h0, h1, l0, l1);
}

// ---------------------------------------------------------------------------
// kernW: conv1(128->32)+BN+ReLU then conv2(32->392)
// ---------------------------------------------------------------------------
#define WXS 0
#define WTS (128 * 68)
#define WWS (128 * 68 + 32 * 68)
#define SMEM_W ((128 * 68 + 32 * 68 + 392 * 32) * 4)

__global__ __launch_bounds__(256, 2) void kernW(
    const float* __restrict__ x,
    const float* __restrict__ c1w, const float* __restrict__ c1b,
    const float* __restrict__ bng, const float* __restrict__ bnb,
    const float* __restrict__ bnm, const float* __restrict__ bnv,
    const float* __restrict__ c2w, const float* __restrict__ c2b)
{
    extern __shared__ float smw[];
    float* xs = smw + WXS;
    float* ts = smw + WTS;
    float* ws = smw + WWS;

    const int bIdx = blockIdx.x / 49;
    const int pc   = blockIdx.x % 49;
    const int p0   = pc * 64;
    const int tid  = threadIdx.x;
    const float* xb = x + (size_t)bIdx * CC * HWP + p0;

    for (int t = tid; t < 128 * 16; t += 256) {
        int c = t >> 4, f = t & 15;
        *(float4*)&xs[c * 68 + f * 4] = *(const float4*)(xb + (size_t)c * HWP + f * 4);
    }
    for (int t = tid; t < 392 * 8; t += 256)
        *(float4*)&ws[t * 4] = *(const float4*)(c2w + t * 4);
    __syncthreads();

    const int pxg = tid & 15, px0 = pxg * 4;

    {
        int r0 = (tid >> 4) * 2;
        float a0[4] = {0.f, 0.f, 0.f, 0.f};
        float a1[4] = {0.f, 0.f, 0.f, 0.f};
        const float* w0p = c1w + (size_t)r0 * 128;
        const float* w1p = w0p + 128;
        #pragma unroll 8
        for (int k4 = 0; k4 < 32; k4++) {
            float wa[4], wb[4];
            *(float4*)wa = *(const float4*)(w0p + k4 * 4);
            *(float4*)wb = *(const float4*)(w1p + k4 * 4);
            #pragma unroll
            for (int kk = 0; kk < 4; kk++) {
                float xv[4];
                *(float4*)xv = *(float4*)&xs[(k4 * 4 + kk) * 68 + px0];
                #pragma unroll
                for (int i = 0; i < 4; i++) {
                    a0[i] = fmaf(wa[kk], xv[i], a0[i]);
                    a1[i] = fmaf(wb[kk], xv[i], a1[i]);
                }
            }
        }
        #pragma unroll
        for (int rr = 0; rr < 2; rr++) {
            int r = r0 + rr;
            float sc = bng[r] * rsqrtf(bnv[r] + 1e-5f);
            float sh = (c1b[r] - bnm[r]) * sc + bnb[r];
            float* ap = rr ? a1 : a0;
            float4 o;
            o.x = fmaxf(fmaf(ap[0], sc, sh), 0.f);
            o.y = fmaxf(fmaf(ap[1], sc, sh), 0.f);
            o.z = fmaxf(fmaf(ap[2], sc, sh), 0.f);
            o.w = fmaxf(fmaf(ap[3], sc, sh), 0.f);
            *(float4*)&ts[r * 68 + px0] = o;
        }
    }
    __syncthreads();

    {
        const int og = tid >> 4;
        for (int ch = 0; ch < 7; ch++) {
            int ocb = ch * 64 + og * 4;
            float a[4][4];
            #pragma unroll
            for (int q = 0; q < 4; q++)
                #pragma unroll
                for (int i = 0; i < 4; i++) a[q][i] = 0.f;
            int oc0 = ocb < 388 ? ocb : 388;
            #pragma unroll
            for (int k4 = 0; k4 < 8; k4++) {
                float wv[4][4];
                #pragma unroll
                for (int q = 0; q < 4; q++)
                    *(float4*)wv[q] = *(float4*)&ws[(oc0 + q) * 32 + k4 * 4];
                #pragma unroll
                for (int kk = 0; kk < 4; kk++) {
                    float xv[4];
                    *(float4*)xv = *(float4*)&ts[(k4 * 4 + kk) * 68 + px0];
                    #pragma unroll
                    for (int q = 0; q < 4; q++)
                        #pragma unroll
                        for (int i = 0; i < 4; i++)
                            a[q][i] = fmaf(wv[q][kk], xv[i], a[q][i]);
                }
            }
            #pragma unroll
            for (int q = 0; q < 4; q++) {
                int oc = oc0 + q;
                if (ocb + q < 392) {
                    float bb = c2b[oc];
                    float4 o = {a[q][0] + bb, a[q][1] + bb, a[q][2] + bb, a[q][3] + bb};
                    *(float4*)(g_wgt + ((size_t)bIdx * OCH + oc) * HWP + p0 + px0) = o;
                }
            }
        }
    }
}

// ---------------------------------------------------------------------------
// kernI v2: involution per (b, h-pair). 224 thr = 14 wq x 8 cslot x 2 rows.
// ---------------------------------------------------------------------------
#define IH_PITCH 516
#define IW_SZ    2744
#define ISM_WS   (32 * IH_PITCH)
#define SMEM_I   ((32 * IH_PITCH + 4 * IW_SZ) * 4)

__global__ __launch_bounds__(224, 2) void kernI(const float* __restrict__ x)
{
    extern __shared__ float smi[];
    float* halo = smi;
    float* wsm  = smi + ISM_WS;

    const int bIdx = blockIdx.x / 28;
    const int hp   = blockIdx.x % 28;
    const int h0   = hp * 2;
    const int tid  = threadIdx.x;
    const float* xb = x + (size_t)bIdx * CC * HWP;

    const int wq    = tid % 14;
    const int s2    = tid / 14;
    const int cslot = s2 & 7;
    const int hr    = s2 >> 3;
    const int w0    = wq * 4;
    const int gl    = cslot >> 2;

    for (int it = 0; it < 4; it++) {
        const int cbase = it * 32;
        if (it) __syncthreads();

        for (int t = tid; t < 4 * IW_SZ; t += 224) {
            int pl = t / IW_SZ;
            int r  = t - pl * IW_SZ;
            int hr2 = pl >> 1, gl2 = pl & 1;
            int k = r / 56, w = r - k * 56;
            wsm[t] = g_wgt[((size_t)bIdx * OCH + (it * 2 + gl2) * KK + k) * HWP
                           + (h0 + hr2) * 56 + w];
        }
        for (int t = tid; t < 32 * 8 * 64; t += 224) {
            int j  = t & 63;
            int r  = (t >> 6) & 7;
            int cl = t >> 9;
            int h2 = h0 + r - 3, w2 = j - 3;
            float v = 0.f;
            if ((unsigned)h2 < 56u && (unsigned)w2 < 56u)
                v = xb[(size_t)(cbase + cl) * HWP + h2 * 56 + w2];
            halo[cl * IH_PITCH + r * 64 + j] = v;
        }
        __syncthreads();

        float acc[4][4];
        #pragma unroll
        for (int wi = 0; wi < 4; wi++)
            #pragma unroll
            for (int c = 0; c < 4; c++) acc[wi][c] = 0.f;

        const float* hb = halo + (cslot * 4) * IH_PITCH + hr * 64 + w0;
        const float* wb = wsm + (hr * 2 + gl) * IW_SZ + w0;

        #pragma unroll
        for (int kh = 0; kh < 7; kh++) {
            float xr[4][12];
            #pragma unroll
            for (int c = 0; c < 4; c++) {
                const float* hq = hb + c * IH_PITCH + kh * 64;
                *(float4*)&xr[c][0] = *(const float4*)hq;
                *(float4*)&xr[c][4] = *(const float4*)(hq + 4);
                *(float4*)&xr[c][8] = *(const float4*)(hq + 8);
            }
            #pragma unroll
            for (int kw = 0; kw < 7; kw++) {
                float4 wv = *(const float4*)(wb + (kh * 7 + kw) * 56);
                #pragma unroll
                for (int c = 0; c < 4; c++) {
                    acc[0][c] = fmaf(wv.x, xr[c][kw],     acc[0][c]);
                    acc[1][c] = fmaf(wv.y, xr[c][kw + 1], acc[1][c]);
                    acc[2][c] = fmaf(wv.z, xr[c][kw + 2], acc[2][c]);
                    acc[3][c] = fmaf(wv.w, xr[c][kw + 3], acc[3][c]);
                }
            }
        }

        size_t pxb = (size_t)bIdx * HWP + (size_t)(h0 + hr) * 56;
        #pragma unroll
        for (int wi = 0; wi < 4; wi++)
            *(float4*)(g_inv + (pxb + w0 + wi) * CC + cbase + cslot * 4) =
                make_float4(acc[wi][0], acc[wi][1], acc[wi][2], acc[wi][3]);
    }
}

// ---------------------------------------------------------------------------
// kernM v4: 64-px CTA, 128 thr (4 warps = 2 rg x 2 cg), 4 CTAs/SM. grid 392.
// smem: b1 2048, b2 512, ysH/ysL 64x272, hsH/hsL 64x144  = 55808 B
// ---------------------------------------------------------------------------
#define MS_B1  0
#define MS_B2  2048
#define MS_YSH 2560
#define MS_YSL (MS_YSH + 17408)
#define MS_HSH (MS_YSL + 17408)
#define MS_HSL (MS_HSH + 9216)
#define SMEM_M (MS_HSL + 9216)

__global__ __launch_bounds__(128, 4) void kernM(
    const float* __restrict__ x,
    const float* __restrict__ b1, const float* __restrict__ b2,
    const float* __restrict__ lnw, const float* __restrict__ lnb,
    float* __restrict__ out)
{
    extern __shared__ char smraw[];
    const uint32_t sb = smem_to_u32(smraw);
    float* b1s = (float*)(smraw + MS_B1);
    float* b2s = (float*)(smraw + MS_B2);

    const int tid = threadIdx.x;
    const int wid = tid >> 5;
    const int l   = tid & 31;
    const size_t p0 = (size_t)blockIdx.x * 64;

    for (int t = tid; t < 512; t += 128) b1s[t] = b1[t];
    if (tid < 128) b2s[tid] = b2[tid];

    // ---- LN + bf16 hi/lo staging of ys (64 px, 2 threads per px) ----
    {
        const int px = tid >> 1, half = tid & 1;
        const float* src = g_inv + (p0 + px) * CC + half * 64;
        float s = 0.f, s2 = 0.f;
        #pragma unroll 4
        for (int i = 0; i < 64; i += 4) {
            float4 v = *(const float4*)(src + i);
            s += v.x + v.y + v.z + v.w;
            s2 = fmaf(v.x, v.x, s2); s2 = fmaf(v.y, v.y, s2);
            s2 = fmaf(v.z, v.z, s2); s2 = fmaf(v.w, v.w, s2);
        }
        s  += __shfl_xor_sync(0xffffffffu, s, 1);
        s2 += __shfl_xor_sync(0xffffffffu, s2, 1);
        float mu  = s * (1.f / 128.f);
        float var = s2 * (1.f / 128.f) - mu * mu;
        float rs  = rsqrtf(var + 1e-6f);
        #pragma unroll 4
        for (int i = 0; i < 64; i += 2) {
            int k = half * 64 + i;
            float y0 = (src[i]     - mu) * rs * lnw[k]     + lnb[k];
            float y1 = (src[i + 1] - mu) * rs * lnw[k + 1] + lnb[k + 1];
            uint32_t hi, lo;
            split_pack(y0, y1, hi, lo);
            *(uint32_t*)(smraw + MS_YSH + px * 272 + k * 2) = hi;
            *(uint32_t*)(smraw + MS_YSL + px * 272 + k * 2) = lo;
        }
    }
    __syncthreads();

    const int rg = wid >> 1;          // 0..1 : rows rg*32..+32
    const int cg = wid & 1;           // col half
    const int r_l   = l & 15;
    const int koffB = (l >> 4) * 16;

    uint32_t aBH[2], aBL[2];
    #pragma unroll
    for (int mt = 0; mt < 2; mt++) {
        uint32_t ro = (rg * 32 + mt * 16 + r_l) * 272 + koffB;
        aBH[mt] = sb + MS_YSH + ro;
        aBL[mt] = sb + MS_YSL + ro;
    }
    uint32_t hBH[2], hBL[2];
    #pragma unroll
    for (int mt = 0; mt < 2; mt++) {
        uint32_t ro = (rg * 32 + mt * 16 + r_l) * 144 + koffB;
        hBH[mt] = sb + MS_HSH + ro;
        hBL[mt] = sb + MS_HSL + ro;
    }

    float acc2[16][4];
    #pragma unroll
    for (int n = 0; n < 16; n++)
        #pragma unroll
        for (int q = 0; q < 4; q++) acc2[n][q] = 0.f;

    const uint4* w1p = g_w1f + l;
    const uint4* w2p = g_w2f + l;

    for (int nb = 0; nb < 8; nb++) {
        const int j0 = nb * 64;

        // ---- GEMM1 ----
        float c1[8][4];
        #pragma unroll
        for (int n = 0; n < 8; n++)
            #pragma unroll
            for (int q = 0; q < 4; q++) c1[n][q] = 0.f;

        #pragma unroll
        for (int kt = 0; kt < 8; kt++) {
            uint32_t ah0[4], ah1[4], al0[4], al1[4];
            ldsm4(ah0, aBH[0] + kt * 32);
            ldsm4(ah1, aBH[1] + kt * 32);
            ldsm4(al0, aBL[0] + kt * 32);
            ldsm4(al1, aBL[1] + kt * 32);
            #pragma unroll
            for (int nt = 0; nt < 4; nt++) {
                uint4 w = w1p[(size_t)(((nb * 8 + kt) * 8) + cg * 4 + nt) * 32];
                mma16816(c1[nt],     ah0, w.x, w.y);
                mma16816(c1[nt],     ah0, w.z, w.w);
                mma16816(c1[nt],     al0, w.x, w.y);
                mma16816(c1[4 + nt], ah1, w.x, w.y);
                mma16816(c1[4 + nt], ah1, w.z, w.w);
                mma16816(c1[4 + nt], al1, w.x, w.y);
            }
        }

        // ---- bias + exact GELU -> hs ----
        #pragma unroll
        for (int mt = 0; mt < 2; mt++) {
            int row = rg * 32 + mt * 16 + (l >> 2);
            #pragma unroll
            for (int nt = 0; nt < 4; nt++) {
                int jc = cg * 32 + nt * 8 + (l & 3) * 2;
                float2 bv = *(const float2*)&b1s[j0 + jc];
                float v0 = c1[mt * 4 + nt][0] + bv.x;
                float v1 = c1[mt * 4 + nt][1] + bv.y;
                float v2 = c1[mt * 4 + nt][2] + bv.x;
                float v3 = c1[mt * 4 + nt][3] + bv.y;
                float g0 = 0.5f * v0 * (1.f + erff(v0 * 0.70710678118654752f));
                float g1 = 0.5f * v1 * (1.f + erff(v1 * 0.70710678118654752f));
                float g2 = 0.5f * v2 * (1.f + erff(v2 * 0.70710678118654752f));
                float g3 = 0.5f * v3 * (1.f + erff(v3 * 0.70710678118654752f));
                uint32_t hi, lo;
                split_pack(g0, g1, hi, lo);
                *(uint32_t*)(smraw + MS_HSH + row * 144 + jc * 2) = hi;
                *(uint32_t*)(smraw + MS_HSL + row * 144 + jc * 2) = lo;
                split_pack(g2, g3, hi, lo);
                *(uint32_t*)(smraw + MS_HSH + (row + 8) * 144 + jc * 2) = hi;
                *(uint32_t*)(smraw + MS_HSL + (row + 8) * 144 + jc * 2) = lo;
            }
        }
        __syncthreads();

        // ---- GEMM2 ----
        #pragma unroll
        for (int kt2 = 0; kt2 < 4; kt2++) {
            uint32_t a0h[4], a1h[4], a0l[4], a1l[4];
            ldsm4(a0h, hBH[0] + kt2 * 32);
            ldsm4(a1h, hBH[1] + kt2 * 32);
            ldsm4(a0l, hBL[0] + kt2 * 32);
            ldsm4(a1l, hBL[1] + kt2 * 32);
            #pragma unroll
            for (int nt = 0; nt < 8; nt++) {
                uint4 w = w2p[(size_t)(((nb * 4 + kt2) * 16) + cg * 8 + nt) * 32];
                mma16816(acc2[nt],     a0h, w.x, w.y);
                mma16816(acc2[nt],     a0h, w.z, w.w);
                mma16816(acc2[nt],     a0l, w.x, w.y);
                mma16816(acc2[8 + nt], a1h, w.x, w.y);
                mma16816(acc2[8 + nt], a1h, w.z, w.w);
                mma16816(acc2[8 + nt], a1l, w.x, w.y);
            }
        }
        __syncthreads();
    }

    // ---- epilogue: + b2 + x, NCHW store ----
    #pragma unroll
    for (int mt = 0; mt < 2; mt++) {
        #pragma unroll
        for (int half = 0; half < 2; half++) {
            int row = rg * 32 + mt * 16 + (l >> 2) + half * 8;
            size_t gpx = p0 + row;
            size_t bI = gpx / HWP, hw = gpx % HWP;
            const float* xb = x + bI * CC * HWP + hw;
            float* ob = out + bI * CC * HWP + hw;
            #pragma unroll
            for (int nt = 0; nt < 8; nt++) {
                int c = cg * 64 + nt * 8 + (l & 3) * 2;
                ob[(size_t)c * HWP] =
                    acc2[mt * 8 + nt][half * 2] + b2s[c] + xb[(size_t)c * HWP];
                ob[(size_t)(c + 1) * HWP] =
                    acc2[mt * 8 + nt][half * 2 + 1] + b2s[c + 1] + xb[(size_t)(c + 1) * HWP];
            }
        }
    }
}

// ---------------------------------------------------------------------------
extern "C" void kernel_launch(void* const* d_in, const int* in_sizes, int n_in,
                              void* d_out, int out_size)
{
    const float* x   = (const float*)d_in[0];
    const float* c1w = (const float*)d_in[1];
    const float* c1b = (const float*)d_in[2];
    const float* bng = (const float*)d_in[3];
    const float* bnb = (const float*)d_in[4];
    const float* bnm = (const float*)d_in[5];
    const float* bnv = (const float*)d_in[6];
    const float* c2w = (const float*)d_in[7];
    const float* c2b = (const float*)d_in[8];
    const float* lnw = (const float*)d_in[9];
    const float* lnb = (const float*)d_in[10];
    const float* w1  = (const float*)d_in[11];
    const float* b1  = (const float*)d_in[12];
    const float* w2  = (const float*)d_in[13];
    const float* b2  = (const float*)d_in[14];
    float* out = (float*)d_out;

    cudaFuncSetAttribute(kernW, cudaFuncAttributeMaxDynamicSharedMemorySize, SMEM_W);
    cudaFuncSetAttribute(kernI, cudaFuncAttributeMaxDynamicSharedMemorySize, SMEM_I);
    cudaFuncSetAttribute(kernM, cudaFuncAttributeMaxDynamicSharedMemorySize, SMEM_M);

    kernP<<<128, 256>>>(w1, w2);
    kernW<<<BB * 49, 256, SMEM_W>>>(x, c1w, c1b, bng, bnb, bnm, bnv, c2w, c2b);
    kernI<<<BB * 28, 224, SMEM_I>>>(x);
    kernM<<<NPIX / 64, 128, SMEM_M>>>(x, b1, b2, lnw, lnb, out);
}

// round 11
// speedup vs baseline: 2.8663x; 1.2724x over previous
#include <cuda_runtime.h>
#include <cuda_bf16.h>
#include <math.h>
#include <stdint.h>

#define BB   8
#define CC   128
#define HH   56
#define WW   56
#define HWP  3136
#define REDC 32
#define GRP  8
#define KK   49
#define OCH  392
#define HID  512
#define NPIX 25088

// scratch
__device__ float g_inv[(size_t)NPIX * CC];
// weights pre-permuted into mma B-fragment layout
__device__ uint4 g_w1f[8 * 8 * 8 * 32];
__device__ uint4 g_w2f[8 * 4 * 16 * 32];

// ======================== helpers ========================
__device__ __forceinline__ uint32_t smem_to_u32(const void* p) {
    uint32_t a;
    asm("{ .reg .u64 t; cvta.to.shared.u64 t, %1; cvt.u32.u64 %0, t; }"
        : "=r"(a) : "l"(p));
    return a;
}
__device__ __forceinline__ void ldsm4(uint32_t r[4], uint32_t addr) {
    asm volatile("ldmatrix.sync.aligned.m8n8.x4.shared.b16 {%0,%1,%2,%3}, [%4];"
        : "=r"(r[0]), "=r"(r[1]), "=r"(r[2]), "=r"(r[3]) : "r"(addr));
}
__device__ __forceinline__ void mma16816(float c[4], const uint32_t a[4],
                                         uint32_t b0, uint32_t b1) {
    asm volatile(
        "mma.sync.aligned.m16n8k16.row.col.f32.bf16.bf16.f32 "
        "{%0,%1,%2,%3}, {%4,%5,%6,%7}, {%8,%9}, {%0,%1,%2,%3};"
        : "+f"(c[0]), "+f"(c[1]), "+f"(c[2]), "+f"(c[3])
        : "r"(a[0]), "r"(a[1]), "r"(a[2]), "r"(a[3]), "r"(b0), "r"(b1));
}
__device__ __forceinline__ void split_pack(float v0, float v1, uint32_t& hi, uint32_t& lo) {
    __nv_bfloat16 h0 = __float2bfloat16(v0);
    __nv_bfloat16 h1 = __float2bfloat16(v1);
    __nv_bfloat16 l0 = __float2bfloat16(v0 - __bfloat162float(h0));
    __nv_bfloat16 l1 = __float2bfloat16(v1 - __bfloat162float(h1));
    __nv_bfloat162 hp; hp.x = h0; hp.y = h1;
    __nv_bfloat162 lp; lp.x = l0; lp.y = l1;
    hi = *(uint32_t*)&hp; lo = *(uint32_t*)&lp;
}

// ---------------------------------------------------------------------------
// kernP: permute w1/w2 into bf16 hi/lo mma fragments
// ---------------------------------------------------------------------------
__global__ __launch_bounds__(256) void kernP(const float* __restrict__ w1,
                                             const float* __restrict__ w2)
{
    int idx = blockIdx.x * 256 + threadIdx.x;   // [0, 32768)
    float v00, v01, v10, v11;
    uint4* dst;
    if (idx < 16384) {
        int l  = idx & 31;
        int nt = (idx >> 5) & 7;
        int kt = (idx >> 8) & 7;
        int c  = idx >> 11;
        int n = c * 64 + nt * 8 + (l >> 2);
        int k = kt * 16 + (l & 3) * 2;
        const float* p = w1 + (size_t)n * 128 + k;
        v00 = p[0]; v01 = p[1]; v10 = p[8]; v11 = p[9];
        dst = g_w1f + idx;
    } else {
        int i2 = idx - 16384;
        int l   = i2 & 31;
        int nt  = (i2 >> 5) & 15;
        int kt2 = (i2 >> 9) & 3;
        int nb  = i2 >> 11;
        int n = nt * 8 + (l >> 2);
        int k = nb * 64 + kt2 * 16 + (l & 3) * 2;
        const float* p = w2 + (size_t)n * 512 + k;
        v00 = p[0]; v01 = p[1]; v10 = p[8]; v11 = p[9];
        dst = g_w2f + i2;
    }
    uint32_t h0, l0, h1, l1;
    split_pack(v00, v01, h0, l0);
    split_pack(v10, v11, h1, l1);
    *dst = make_uint4(h0, h1, l0, l1);
}

// ---------------------------------------------------------------------------
// kernFI: fused conv1+BN+ReLU -> conv2 (per group) -> involution.
// Block = (b, h). 224 threads. No g_wgt round trip.
// smem floats: ts[32][60] @0 ; region A @1920:
//   phase1: xs[128][60] (7680)
//   per-g : wg[49][60] (2940) @1920 ; halo[16][452] (7232) @4860
// ---------------------------------------------------------------------------
#define F_TS 0
#define F_A  1920
#define F_XS F_A
#define F_WG F_A
#define F_HA (F_A + 2940)
#define F_TOT (F_A + 2940 + 7232)
#define SMEM_F (F_TOT * 4)

__global__ __launch_bounds__(224, 3) void kernFI(
    const float* __restrict__ x,
    const float* __restrict__ c1w, const float* __restrict__ c1b,
    const float* __restrict__ bng, const float* __restrict__ bnb,
    const float* __restrict__ bnm, const float* __restrict__ bnv,
    const float* __restrict__ c2w, const float* __restrict__ c2b)
{
    extern __shared__ float smf[];
    float* ts = smf + F_TS;
    float* xs = smf + F_XS;
    float* wg = smf + F_WG;
    float* ha = smf + F_HA;

    const int bIdx = blockIdx.x / 56;
    const int h    = blockIdx.x % 56;
    const int tid  = threadIdx.x;
    const float* xb = x + (size_t)bIdx * CC * HWP;

    // ---- stage xs[128][60]: row h, all 128 channels ----
    for (int i = tid; i < 128 * 14; i += 224) {
        int c = i / 14, f = i % 14;
        *(float4*)&xs[c * 60 + f * 4] =
            *(const float4*)(xb + (size_t)c * HWP + h * 56 + f * 4);
    }
    __syncthreads();

    // ---- conv1 (128->32) + BN + ReLU -> ts[32][60] ----
    {
        const int wh = tid % 28, rg = tid / 28;    // 28 x 8
        const int w0 = wh * 2, r0 = rg * 4;
        float a[4][2] = {{0.f,0.f},{0.f,0.f},{0.f,0.f},{0.f,0.f}};
        #pragma unroll 4
        for (int k4 = 0; k4 < 32; k4++) {
            float wv[4][4];
            #pragma unroll
            for (int q = 0; q < 4; q++)
                *(float4*)wv[q] = *(const float4*)(c1w + (size_t)(r0 + q) * 128 + k4 * 4);
            #pragma unroll
            for (int kk = 0; kk < 4; kk++) {
                float x0 = xs[(k4 * 4 + kk) * 60 + w0];
                float x1 = xs[(k4 * 4 + kk) * 60 + w0 + 1];
                #pragma unroll
                for (int q = 0; q < 4; q++) {
                    a[q][0] = fmaf(wv[q][kk], x0, a[q][0]);
                    a[q][1] = fmaf(wv[q][kk], x1, a[q][1]);
                }
            }
        }
        #pragma unroll
        for (int q = 0; q < 4; q++) {
            int r = r0 + q;
            float sc = bng[r] * rsqrtf(bnv[r] + 1e-5f);
            float sh = (c1b[r] - bnm[r]) * sc + bnb[r];
            ts[r * 60 + w0]     = fmaxf(fmaf(a[q][0], sc, sh), 0.f);
            ts[r * 60 + w0 + 1] = fmaxf(fmaf(a[q][1], sc, sh), 0.f);
        }
    }
    __syncthreads();   // ts ready; xs dead

    const int oq  = tid / 14;          // conv2: 0..15 (13 active)
    const int wq4 = (tid % 14) * 4;
    const int ci  = tid & 15;          // involution channel
    const int w0i = (tid >> 4) * 4;    // involution w base (0..13)*4
    const size_t pxb = (size_t)bIdx * HWP + (size_t)h * 56;

    for (int g = 0; g < 8; g++) {
        // ---- conv2: this group's 49 oc x 56 px -> wg ----
        if (oq < 13) {
            int ocl = oq * 4 < 45 ? oq * 4 : 45;   // clamp: 45..48 max
            float a[4][4];
            #pragma unroll
            for (int q = 0; q < 4; q++)
                #pragma unroll
                for (int i = 0; i < 4; i++) a[q][i] = 0.f;
            #pragma unroll
            for (int r4 = 0; r4 < 8; r4++) {
                float wv[4][4];
                #pragma unroll
                for (int q = 0; q < 4; q++)
                    *(float4*)wv[q] =
                        *(const float4*)(c2w + (size_t)(g * 49 + ocl + q) * 32 + r4 * 4);
                #pragma unroll
                for (int kk = 0; kk < 4; kk++) {
                    float tv[4];
                    *(float4*)tv = *(float4*)&ts[(r4 * 4 + kk) * 60 + wq4];
                    #pragma unroll
                    for (int q = 0; q < 4; q++)
                        #pragma unroll
                        for (int i = 0; i < 4; i++)
                            a[q][i] = fmaf(wv[q][kk], tv[i], a[q][i]);
                }
            }
            #pragma unroll
            for (int q = 0; q < 4; q++) {
                float bb = c2b[g * 49 + ocl + q];
                *(float4*)&wg[(ocl + q) * 60 + wq4] =
                    make_float4(a[q][0] + bb, a[q][1] + bb, a[q][2] + bb, a[q][3] + bb);
            }
        }
        // ---- halo: 16 ch x 7 rows x 64 cols (zero-padded) ----
        for (int t = tid; t < 16 * 448; t += 224) {
            int j = t & 63;
            int r = (t >> 6) % 7;
            int c = t / 448;
            int h2 = h + r - 3, w2 = j - 3;
            float v = 0.f;
            if ((unsigned)h2 < 56u && (unsigned)w2 < 56u)
                v = xb[(size_t)(g * 16 + c) * HWP + h2 * 56 + w2];
            ha[c * 452 + r * 64 + j] = v;
        }
        __syncthreads();

        // ---- involution: 1 ch x 4 w per thread ----
        {
            float acc[4] = {0.f, 0.f, 0.f, 0.f};
            const float* hb = ha + ci * 452;
            #pragma unroll
            for (int kh = 0; kh < 7; kh++) {
                float xr[12];
                *(float4*)&xr[0] = *(float4*)&hb[kh * 64 + w0i];
                *(float4*)&xr[4] = *(float4*)&hb[kh * 64 + w0i + 4];
                *(float4*)&xr[8] = *(float4*)&hb[kh * 64 + w0i + 8];
                #pragma unroll
                for (int kw = 0; kw < 7; kw++) {
                    float4 wv = *(float4*)&wg[(kh * 7 + kw) * 60 + w0i];
                    acc[0] = fmaf(wv.x, xr[kw],     acc[0]);
                    acc[1] = fmaf(wv.y, xr[kw + 1], acc[1]);
                    acc[2] = fmaf(wv.z, xr[kw + 2], acc[2]);
                    acc[3] = fmaf(wv.w, xr[kw + 3], acc[3]);
                }
            }
            #pragma unroll
            for (int wi = 0; wi < 4; wi++)
                g_inv[(pxb + w0i + wi) * CC + g * 16 + ci] = acc[wi];
        }
        __syncthreads();
    }
}

// ---------------------------------------------------------------------------
// kernM v4: 64-px CTA, 128 thr (4 warps = 2 rg x 2 cg). Unchanged from R10.
// ---------------------------------------------------------------------------
#define MS_B1  0
#define MS_B2  2048
#define MS_YSH 2560
#define MS_YSL (MS_YSH + 17408)
#define MS_HSH (MS_YSL + 17408)
#define MS_HSL (MS_HSH + 9216)
#define SMEM_M (MS_HSL + 9216)

__global__ __launch_bounds__(128, 4) void kernM(
    const float* __restrict__ x,
    const float* __restrict__ b1, const float* __restrict__ b2,
    const float* __restrict__ lnw, const float* __restrict__ lnb,
    float* __restrict__ out)
{
    extern __shared__ char smraw[];
    const uint32_t sb = smem_to_u32(smraw);
    float* b1s = (float*)(smraw + MS_B1);
    float* b2s = (float*)(smraw + MS_B2);

    const int tid = threadIdx.x;
    const int wid = tid >> 5;
    const int l   = tid & 31;
    const size_t p0 = (size_t)blockIdx.x * 64;

    for (int t = tid; t < 512; t += 128) b1s[t] = b1[t];
    if (tid < 128) b2s[tid] = b2[tid];

    // ---- LN + bf16 hi/lo staging of ys ----
    {
        const int px = tid >> 1, half = tid & 1;
        const float* src = g_inv + (p0 + px) * CC + half * 64;
        float s = 0.f, s2 = 0.f;
        #pragma unroll 4
        for (int i = 0; i < 64; i += 4) {
            float4 v = *(const float4*)(src + i);
            s += v.x + v.y + v.z + v.w;
            s2 = fmaf(v.x, v.x, s2); s2 = fmaf(v.y, v.y, s2);
            s2 = fmaf(v.z, v.z, s2); s2 = fmaf(v.w, v.w, s2);
        }
        s  += __shfl_xor_sync(0xffffffffu, s, 1);
        s2 += __shfl_xor_sync(0xffffffffu, s2, 1);
        float mu  = s * (1.f / 128.f);
        float var = s2 * (1.f / 128.f) - mu * mu;
        float rs  = rsqrtf(var + 1e-6f);
        #pragma unroll 4
        for (int i = 0; i < 64; i += 2) {
            int k = half * 64 + i;
            float y0 = (src[i]     - mu) * rs * lnw[k]     + lnb[k];
            float y1 = (src[i + 1] - mu) * rs * lnw[k + 1] + lnb[k + 1];
            uint32_t hi, lo;
            split_pack(y0, y1, hi, lo);
            *(uint32_t*)(smraw + MS_YSH + px * 272 + k * 2) = hi;
            *(uint32_t*)(smraw + MS_YSL + px * 272 + k * 2) = lo;
        }
    }
    __syncthreads();

    const int rg = wid >> 1;
    const int cg = wid & 1;
    const int r_l   = l & 15;
    const int koffB = (l >> 4) * 16;

    uint32_t aBH[2], aBL[2];
    #pragma unroll
    for (int mt = 0; mt < 2; mt++) {
        uint32_t ro = (rg * 32 + mt * 16 + r_l) * 272 + koffB;
        aBH[mt] = sb + MS_YSH + ro;
        aBL[mt] = sb + MS_YSL + ro;
    }
    uint32_t hBH[2], hBL[2];
    #pragma unroll
    for (int mt = 0; mt < 2; mt++) {
        uint32_t ro = (rg * 32 + mt * 16 + r_l) * 144 + koffB;
        hBH[mt] = sb + MS_HSH + ro;
        hBL[mt] = sb + MS_HSL + ro;
    }

    float acc2[16][4];
    #pragma unroll
    for (int n = 0; n < 16; n++)
        #pragma unroll
        for (int q = 0; q < 4; q++) acc2[n][q] = 0.f;

    const uint4* w1p = g_w1f + l;
    const uint4* w2p = g_w2f + l;

    for (int nb = 0; nb < 8; nb++) {
        const int j0 = nb * 64;

        // ---- GEMM1 ----
        float c1[8][4];
        #pragma unroll
        for (int n = 0; n < 8; n++)
            #pragma unroll
            for (int q = 0; q < 4; q++) c1[n][q] = 0.f;

        #pragma unroll
        for (int kt = 0; kt < 8; kt++) {
            uint32_t ah0[4], ah1[4], al0[4], al1[4];
            ldsm4(ah0, aBH[0] + kt * 32);
            ldsm4(ah1, aBH[1] + kt * 32);
            ldsm4(al0, aBL[0] + kt * 32);
            ldsm4(al1, aBL[1] + kt * 32);
            #pragma unroll
            for (int nt = 0; nt < 4; nt++) {
                uint4 w = w1p[(size_t)(((nb * 8 + kt) * 8) + cg * 4 + nt) * 32];
                mma16816(c1[nt],     ah0, w.x, w.y);
                mma16816(c1[nt],     ah0, w.z, w.w);
                mma16816(c1[nt],     al0, w.x, w.y);
                mma16816(c1[4 + nt], ah1, w.x, w.y);
                mma16816(c1[4 + nt], ah1, w.z, w.w);
                mma16816(c1[4 + nt], al1, w.x, w.y);
            }
        }

        // ---- bias + exact GELU -> hs ----
        #pragma unroll
        for (int mt = 0; mt < 2; mt++) {
            int row = rg * 32 + mt * 16 + (l >> 2);
            #pragma unroll
            for (int nt = 0; nt < 4; nt++) {
                int jc = cg * 32 + nt * 8 + (l & 3) * 2;
                float2 bv = *(const float2*)&b1s[j0 + jc];
                float v0 = c1[mt * 4 + nt][0] + bv.x;
                float v1 = c1[mt * 4 + nt][1] + bv.y;
                float v2 = c1[mt * 4 + nt][2] + bv.x;
                float v3 = c1[mt * 4 + nt][3] + bv.y;
                float g0 = 0.5f * v0 * (1.f + erff(v0 * 0.70710678118654752f));
                float g1 = 0.5f * v1 * (1.f + erff(v1 * 0.70710678118654752f));
                float g2 = 0.5f * v2 * (1.f + erff(v2 * 0.70710678118654752f));
                float g3 = 0.5f * v3 * (1.f + erff(v3 * 0.70710678118654752f));
                uint32_t hi, lo;
                split_pack(g0, g1, hi, lo);
                *(uint32_t*)(smraw + MS_HSH + row * 144 + jc * 2) = hi;
                *(uint32_t*)(smraw + MS_HSL + row * 144 + jc * 2) = lo;
                split_pack(g2, g3, hi, lo);
                *(uint32_t*)(smraw + MS_HSH + (row + 8) * 144 + jc * 2) = hi;
                *(uint32_t*)(smraw + MS_HSL + (row + 8) * 144 + jc * 2) = lo;
            }
        }
        __syncthreads();

        // ---- GEMM2 ----
        #pragma unroll
        for (int kt2 = 0; kt2 < 4; kt2++) {
            uint32_t a0h[4], a1h[4], a0l[4], a1l[4];
            ldsm4(a0h, hBH[0] + kt2 * 32);
            ldsm4(a1h, hBH[1] + kt2 * 32);
            ldsm4(a0l, hBL[0] + kt2 * 32);
            ldsm4(a1l, hBL[1] + kt2 * 32);
            #pragma unroll
            for (int nt = 0; nt < 8; nt++) {
                uint4 w = w2p[(size_t)(((nb * 4 + kt2) * 16) + cg * 8 + nt) * 32];
                mma16816(acc2[nt],     a0h, w.x, w.y);
                mma16816(acc2[nt],     a0h, w.z, w.w);
                mma16816(acc2[nt],     a0l, w.x, w.y);
                mma16816(acc2[8 + nt], a1h, w.x, w.y);
                mma16816(acc2[8 + nt], a1h, w.z, w.w);
                mma16816(acc2[8 + nt], a1l, w.x, w.y);
            }
        }
        __syncthreads();
    }

    // ---- epilogue: + b2 + x, NCHW store ----
    #pragma unroll
    for (int mt = 0; mt < 2; mt++) {
        #pragma unroll
        for (int half = 0; half < 2; half++) {
            int row = rg * 32 + mt * 16 + (l >> 2) + half * 8;
            size_t gpx = p0 + row;
            size_t bI = gpx / HWP, hw = gpx % HWP;
            const float* xb = x + bI * CC * HWP + hw;
            float* ob = out + bI * CC * HWP + hw;
            #pragma unroll
            for (int nt = 0; nt < 8; nt++) {
                int c = cg * 64 + nt * 8 + (l & 3) * 2;
                ob[(size_t)c * HWP] =
                    acc2[mt * 8 + nt][half * 2] + b2s[c] + xb[(size_t)c * HWP];
                ob[(size_t)(c + 1) * HWP] =
                    acc2[mt * 8 + nt][half * 2 + 1] + b2s[c + 1] + xb[(size_t)(c + 1) * HWP];
            }
        }
    }
}

// ---------------------------------------------------------------------------
extern "C" void kernel_launch(void* const* d_in, const int* in_sizes, int n_in,
                              void* d_out, int out_size)
{
    const float* x   = (const float*)d_in[0];
    const float* c1w = (const float*)d_in[1];
    const float* c1b = (const float*)d_in[2];
    const float* bng = (const float*)d_in[3];
    const float* bnb = (const float*)d_in[4];
    const float* bnm = (const float*)d_in[5];
    const float* bnv = (const float*)d_in[6];
    const float* c2w = (const float*)d_in[7];
    const float* c2b = (const float*)d_in[8];
    const float* lnw = (const float*)d_in[9];
    const float* lnb = (const float*)d_in[10];
    const float* w1  = (const float*)d_in[11];
    const float* b1  = (const float*)d_in[12];
    const float* w2  = (const float*)d_in[13];
    const float* b2  = (const float*)d_in[14];
    float* out = (float*)d_out;

    cudaFuncSetAttribute(kernFI, cudaFuncAttributeMaxDynamicSharedMemorySize, SMEM_F);
    cudaFuncSetAttribute(kernM, cudaFuncAttributeMaxDynamicSharedMemorySize, SMEM_M);

    kernP<<<128, 256>>>(w1, w2);
    kernFI<<<BB * HH, 224, SMEM_F>>>(x, c1w, c1b, bng, bnb, bnm, bnv, c2w, c2b);
    kernM<<<NPIX / 64, 128, SMEM_M>>>(x, b1, b2, lnw, lnb, out);
}

// round 13
// speedup vs baseline: 3.0301x; 1.0571x over previous
#include <cuda_runtime.h>
#include <cuda_bf16.h>
#include <math.h>
#include <stdint.h>

#define BB   8
#define CC   128
#define HH   56
#define WW   56
#define HWP  3136
#define REDC 32
#define GRP  8
#define KK   49
#define OCH  392
#define HID  512
#define NPIX 25088

// scratch
__device__ float g_inv[(size_t)NPIX * CC];
// weights pre-permuted into mma B-fragment layout
__device__ uint4 g_w1f[8 * 8 * 8 * 32];
__device__ uint4 g_w2f[8 * 4 * 16 * 32];

// ======================== helpers ========================
__device__ __forceinline__ uint32_t smem_to_u32(const void* p) {
    uint32_t a;
    asm("{ .reg .u64 t; cvta.to.shared.u64 t, %1; cvt.u32.u64 %0, t; }"
        : "=r"(a) : "l"(p));
    return a;
}
__device__ __forceinline__ void ldsm4(uint32_t r[4], uint32_t addr) {
    asm volatile("ldmatrix.sync.aligned.m8n8.x4.shared.b16 {%0,%1,%2,%3}, [%4];"
        : "=r"(r[0]), "=r"(r[1]), "=r"(r[2]), "=r"(r[3]) : "r"(addr));
}
__device__ __forceinline__ void mma16816(float c[4], const uint32_t a[4],
                                         uint32_t b0, uint32_t b1) {
    asm volatile(
        "mma.sync.aligned.m16n8k16.row.col.f32.bf16.bf16.f32 "
        "{%0,%1,%2,%3}, {%4,%5,%6,%7}, {%8,%9}, {%0,%1,%2,%3};"
        : "+f"(c[0]), "+f"(c[1]), "+f"(c[2]), "+f"(c[3])
        : "r"(a[0]), "r"(a[1]), "r"(a[2]), "r"(a[3]), "r"(b0), "r"(b1));
}
__device__ __forceinline__ void split_pack(float v0, float v1, uint32_t& hi, uint32_t& lo) {
    __nv_bfloat16 h0 = __float2bfloat16(v0);
    __nv_bfloat16 h1 = __float2bfloat16(v1);
    __nv_bfloat16 l0 = __float2bfloat16(v0 - __bfloat162float(h0));
    __nv_bfloat16 l1 = __float2bfloat16(v1 - __bfloat162float(h1));
    __nv_bfloat162 hp; hp.x = h0; hp.y = h1;
    __nv_bfloat162 lp; lp.x = l0; lp.y = l1;
    hi = *(uint32_t*)&hp; lo = *(uint32_t*)&lp;
}

// ---------------------------------------------------------------------------
// kernP: permute w1/w2 into bf16 hi/lo mma fragments
// ---------------------------------------------------------------------------
__global__ __launch_bounds__(256) void kernP(const float* __restrict__ w1,
                                             const float* __restrict__ w2)
{
    int idx = blockIdx.x * 256 + threadIdx.x;   // [0, 32768)
    float v00, v01, v10, v11;
    uint4* dst;
    if (idx < 16384) {
        int l  = idx & 31;
        int nt = (idx >> 5) & 7;
        int kt = (idx >> 8) & 7;
        int c  = idx >> 11;
        int n = c * 64 + nt * 8 + (l >> 2);
        int k = kt * 16 + (l & 3) * 2;
        const float* p = w1 + (size_t)n * 128 + k;
        v00 = p[0]; v01 = p[1]; v10 = p[8]; v11 = p[9];
        dst = g_w1f + idx;
    } else {
        int i2 = idx - 16384;
        int l   = i2 & 31;
        int nt  = (i2 >> 5) & 15;
        int kt2 = (i2 >> 9) & 3;
        int nb  = i2 >> 11;
        int n = nt * 8 + (l >> 2);
        int k = nb * 64 + kt2 * 16 + (l & 3) * 2;
        const float* p = w2 + (size_t)n * 512 + k;
        v00 = p[0]; v01 = p[1]; v10 = p[8]; v11 = p[9];
        dst = g_w2f + i2;
    }
    uint32_t h0, l0, h1, l1;
    split_pack(v00, v01, h0, l0);
    split_pack(v10, v11, h1, l1);
    *dst = make_uint4(h0, h1, l0, l1);
}

// ---------------------------------------------------------------------------
// kernFI: fused conv1+BN+ReLU -> conv2 (per group) -> involution.
// Block = (b, h). 224 threads, 4 CTAs/SM -> single wave (592 slots >= 448).
// ---------------------------------------------------------------------------
#define F_TS 0
#define F_A  1920
#define F_XS F_A
#define F_WG F_A
#define F_HA (F_A + 2940)
#define F_TOT (F_A + 2940 + 7232)
#define SMEM_F (F_TOT * 4)

__global__ __launch_bounds__(224, 4) void kernFI(
    const float* __restrict__ x,
    const float* __restrict__ c1w, const float* __restrict__ c1b,
    const float* __restrict__ bng, const float* __restrict__ bnb,
    const float* __restrict__ bnm, const float* __restrict__ bnv,
    const float* __restrict__ c2w, const float* __restrict__ c2b)
{
    extern __shared__ float smf[];
    float* ts = smf + F_TS;
    float* xs = smf + F_XS;
    float* wg = smf + F_WG;
    float* ha = smf + F_HA;

    const int bIdx = blockIdx.x / 56;
    const int h    = blockIdx.x % 56;
    const int tid  = threadIdx.x;
    const float* xb = x + (size_t)bIdx * CC * HWP;

    // ---- stage xs[128][60]: row h, all 128 channels ----
    for (int i = tid; i < 128 * 14; i += 224) {
        int c = i / 14, f = i % 14;
        *(float4*)&xs[c * 60 + f * 4] =
            *(const float4*)(xb + (size_t)c * HWP + h * 56 + f * 4);
    }
    __syncthreads();

    // ---- conv1 (128->32) + BN + ReLU -> ts[32][60] ----
    {
        const int wh = tid % 28, rg = tid / 28;
        const int w0 = wh * 2, r0 = rg * 4;
        float a[4][2] = {{0.f,0.f},{0.f,0.f},{0.f,0.f},{0.f,0.f}};
        #pragma unroll 4
        for (int k4 = 0; k4 < 32; k4++) {
            float wv[4][4];
            #pragma unroll
            for (int q = 0; q < 4; q++)
                *(float4*)wv[q] = *(const float4*)(c1w + (size_t)(r0 + q) * 128 + k4 * 4);
            #pragma unroll
            for (int kk = 0; kk < 4; kk++) {
                float x0 = xs[(k4 * 4 + kk) * 60 + w0];
                float x1 = xs[(k4 * 4 + kk) * 60 + w0 + 1];
                #pragma unroll
                for (int q = 0; q < 4; q++) {
                    a[q][0] = fmaf(wv[q][kk], x0, a[q][0]);
                    a[q][1] = fmaf(wv[q][kk], x1, a[q][1]);
                }
            }
        }
        #pragma unroll
        for (int q = 0; q < 4; q++) {
            int r = r0 + q;
            float sc = bng[r] * rsqrtf(bnv[r] + 1e-5f);
            float sh = (c1b[r] - bnm[r]) * sc + bnb[r];
            ts[r * 60 + w0]     = fmaxf(fmaf(a[q][0], sc, sh), 0.f);
            ts[r * 60 + w0 + 1] = fmaxf(fmaf(a[q][1], sc, sh), 0.f);
        }
    }
    __syncthreads();   // ts ready; xs dead

    const int oq  = tid / 14;
    const int wq4 = (tid % 14) * 4;
    const int ci  = tid & 15;
    const int w0i = (tid >> 4) * 4;
    const size_t pxb = (size_t)bIdx * HWP + (size_t)h * 56;

    for (int g = 0; g < 8; g++) {
        // ---- conv2: this group's 49 oc x 56 px -> wg ----
        if (oq < 13) {
            int ocl = oq * 4 < 45 ? oq * 4 : 45;
            float a[4][4];
            #pragma unroll
            for (int q = 0; q < 4; q++)
                #pragma unroll
                for (int i = 0; i < 4; i++) a[q][i] = 0.f;
            #pragma unroll
            for (int r4 = 0; r4 < 8; r4++) {
                float wv[4][4];
                #pragma unroll
                for (int q = 0; q < 4; q++)
                    *(float4*)wv[q] =
                        *(const float4*)(c2w + (size_t)(g * 49 + ocl + q) * 32 + r4 * 4);
                #pragma unroll
                for (int kk = 0; kk < 4; kk++) {
                    float tv[4];
                    *(float4*)tv = *(float4*)&ts[(r4 * 4 + kk) * 60 + wq4];
                    #pragma unroll
                    for (int q = 0; q < 4; q++)
                        #pragma unroll
                        for (int i = 0; i < 4; i++)
                            a[q][i] = fmaf(wv[q][kk], tv[i], a[q][i]);
                }
            }
            #pragma unroll
            for (int q = 0; q < 4; q++) {
                float bb = c2b[g * 49 + ocl + q];
                *(float4*)&wg[(ocl + q) * 60 + wq4] =
                    make_float4(a[q][0] + bb, a[q][1] + bb, a[q][2] + bb, a[q][3] + bb);
            }
        }
        // ---- halo: 16 ch x 7 rows x 64 cols (zero-padded) ----
        for (int t = tid; t < 16 * 448; t += 224) {
            int j = t & 63;
            int r = (t >> 6) % 7;
            int c = t / 448;
            int h2 = h + r - 3, w2 = j - 3;
            float v = 0.f;
            if ((unsigned)h2 < 56u && (unsigned)w2 < 56u)
                v = xb[(size_t)(g * 16 + c) * HWP + h2 * 56 + w2];
            ha[c * 452 + r * 64 + j] = v;
        }
        __syncthreads();

        // ---- involution: 1 ch x 4 w per thread ----
        {
            float acc[4] = {0.f, 0.f, 0.f, 0.f};
            const float* hb = ha + ci * 452;
            #pragma unroll
            for (int kh = 0; kh < 7; kh++) {
                float xr[12];
                *(float4*)&xr[0] = *(float4*)&hb[kh * 64 + w0i];
                *(float4*)&xr[4] = *(float4*)&hb[kh * 64 + w0i + 4];
                *(float4*)&xr[8] = *(float4*)&hb[kh * 64 + w0i + 8];
                #pragma unroll
                for (int kw = 0; kw < 7; kw++) {
                    float4 wv = *(float4*)&wg[(kh * 7 + kw) * 60 + w0i];
                    acc[0] = fmaf(wv.x, xr[kw],     acc[0]);
                    acc[1] = fmaf(wv.y, xr[kw + 1], acc[1]);
                    acc[2] = fmaf(wv.z, xr[kw + 2], acc[2]);
                    acc[3] = fmaf(wv.w, xr[kw + 3], acc[3]);
                }
            }
            #pragma unroll
            for (int wi = 0; wi < 4; wi++)
                g_inv[(pxb + w0i + wi) * CC + g * 16 + ci] = acc[wi];
        }
        __syncthreads();
    }
}

// ---------------------------------------------------------------------------
// kernM v5: 64-px CTA, 4 warps. Weight-fragment double buffering.
// ---------------------------------------------------------------------------
#define MS_B1  0
#define MS_B2  2048
#define MS_YSH 2560
#define MS_YSL (MS_YSH + 17408)
#define MS_HSH (MS_YSL + 17408)
#define MS_HSL (MS_HSH + 9216)
#define SMEM_M (MS_HSL + 9216)

__global__ __launch_bounds__(128, 3) void kernM(
    const float* __restrict__ x,
    const float* __restrict__ b1, const float* __restrict__ b2,
    const float* __restrict__ lnw, const float* __restrict__ lnb,
    float* __restrict__ out)
{
    extern __shared__ char smraw[];
    const uint32_t sb = smem_to_u32(smraw);
    float* b1s = (float*)(smraw + MS_B1);
    float* b2s = (float*)(smraw + MS_B2);

    const int tid = threadIdx.x;
    const int wid = tid >> 5;
    const int l   = tid & 31;
    const size_t p0 = (size_t)blockIdx.x * 64;

    for (int t = tid; t < 512; t += 128) b1s[t] = b1[t];
    if (tid < 128) b2s[tid] = b2[tid];

    // ---- LN + bf16 hi/lo staging of ys ----
    {
        const int px = tid >> 1, half = tid & 1;
        const float* src = g_inv + (p0 + px) * CC + half * 64;
        float s = 0.f, s2 = 0.f;
        #pragma unroll 4
        for (int i = 0; i < 64; i += 4) {
            float4 v = *(const float4*)(src + i);
            s += v.x + v.y + v.z + v.w;
            s2 = fmaf(v.x, v.x, s2); s2 = fmaf(v.y, v.y, s2);
            s2 = fmaf(v.z, v.z, s2); s2 = fmaf(v.w, v.w, s2);
        }
        s  += __shfl_xor_sync(0xffffffffu, s, 1);
        s2 += __shfl_xor_sync(0xffffffffu, s2, 1);
        float mu  = s * (1.f / 128.f);
        float var = s2 * (1.f / 128.f) - mu * mu;
        float rs  = rsqrtf(var + 1e-6f);
        #pragma unroll 4
        for (int i = 0; i < 64; i += 2) {
            int k = half * 64 + i;
            float y0 = (src[i]     - mu) * rs * lnw[k]     + lnb[k];
            float y1 = (src[i + 1] - mu) * rs * lnw[k + 1] + lnb[k + 1];
            uint32_t hi, lo;
            split_pack(y0, y1, hi, lo);
            *(uint32_t*)(smraw + MS_YSH + px * 272 + k * 2) = hi;
            *(uint32_t*)(smraw + MS_YSL + px * 272 + k * 2) = lo;
        }
    }
    __syncthreads();

    const int rg = wid >> 1;
    const int cg = wid & 1;
    const int r_l   = l & 15;
    const int koffB = (l >> 4) * 16;

    uint32_t aBH[2], aBL[2];
    #pragma unroll
    for (int mt = 0; mt < 2; mt++) {
        uint32_t ro = (rg * 32 + mt * 16 + r_l) * 272 + koffB;
        aBH[mt] = sb + MS_YSH + ro;
        aBL[mt] = sb + MS_YSL + ro;
    }
    uint32_t hBH[2], hBL[2];
    #pragma unroll
    for (int mt = 0; mt < 2; mt++) {
        uint32_t ro = (rg * 32 + mt * 16 + r_l) * 144 + koffB;
        hBH[mt] = sb + MS_HSH + ro;
        hBL[mt] = sb + MS_HSL + ro;
    }

    float acc2[16][4];
    #pragma unroll
    for (int n = 0; n < 16; n++)
        #pragma unroll
        for (int q = 0; q < 4; q++) acc2[n][q] = 0.f;

    const uint4* w1p = g_w1f + l;
    const uint4* w2p = g_w2f + l;

    for (int nb = 0; nb < 8; nb++) {
        const int j0 = nb * 64;
        const uint4* b1w = w1p + (size_t)(nb * 8 * 8 + cg * 4) * 32;
        const uint4* b2w = w2p + (size_t)(nb * 4 * 16 + cg * 8) * 32;

        // ---- GEMM1: double-buffered weight fragments ----
        float c1[8][4];
        #pragma unroll
        for (int n = 0; n < 8; n++)
            #pragma unroll
            for (int q = 0; q < 4; q++) c1[n][q] = 0.f;

        uint4 wc[4];
        #pragma unroll
        for (int i = 0; i < 4; i++) wc[i] = b1w[(size_t)i * 32];

        #pragma unroll
        for (int kt = 0; kt < 8; kt++) {
            uint32_t ah0[4], ah1[4], al0[4], al1[4];
            ldsm4(ah0, aBH[0] + kt * 32);
            ldsm4(ah1, aBH[1] + kt * 32);
            ldsm4(al0, aBL[0] + kt * 32);
            ldsm4(al1, aBL[1] + kt * 32);
            uint4 wn[4];
            if (kt < 7) {
                #pragma unroll
                for (int i = 0; i < 4; i++)
                    wn[i] = b1w[(size_t)((kt + 1) * 8 + i) * 32];
            }
            #pragma unroll
            for (int nt = 0; nt < 4; nt++) {
                mma16816(c1[nt],     ah0, wc[nt].x, wc[nt].y);
                mma16816(c1[nt],     ah0, wc[nt].z, wc[nt].w);
                mma16816(c1[nt],     al0, wc[nt].x, wc[nt].y);
                mma16816(c1[4 + nt], ah1, wc[nt].x, wc[nt].y);
                mma16816(c1[4 + nt], ah1, wc[nt].z, wc[nt].w);
                mma16816(c1[4 + nt], al1, wc[nt].x, wc[nt].y);
            }
            #pragma unroll
            for (int i = 0; i < 4; i++) wc[i] = wn[i];
        }

        // ---- bias + exact GELU -> hs ----
        #pragma unroll
        for (int mt = 0; mt < 2; mt++) {
            int row = rg * 32 + mt * 16 + (l >> 2);
            #pragma unroll
            for (int nt = 0; nt < 4; nt++) {
                int jc = cg * 32 + nt * 8 + (l & 3) * 2;
                float2 bv = *(const float2*)&b1s[j0 + jc];
                float v0 = c1[mt * 4 + nt][0] + bv.x;
                float v1 = c1[mt * 4 + nt][1] + bv.y;
                float v2 = c1[mt * 4 + nt][2] + bv.x;
                float v3 = c1[mt * 4 + nt][3] + bv.y;
                float g0 = 0.5f * v0 * (1.f + erff(v0 * 0.70710678118654752f));
                float g1 = 0.5f * v1 * (1.f + erff(v1 * 0.70710678118654752f));
                float g2 = 0.5f * v2 * (1.f + erff(v2 * 0.70710678118654752f));
                float g3 = 0.5f * v3 * (1.f + erff(v3 * 0.70710678118654752f));
                uint32_t hi, lo;
                split_pack(g0, g1, hi, lo);
                *(uint32_t*)(smraw + MS_HSH + row * 144 + jc * 2) = hi;
                *(uint32_t*)(smraw + MS_HSL + row * 144 + jc * 2) = lo;
                split_pack(g2, g3, hi, lo);
                *(uint32_t*)(smraw + MS_HSH + (row + 8) * 144 + jc * 2) = hi;
                *(uint32_t*)(smraw + MS_HSL + (row + 8) * 144 + jc * 2) = lo;
            }
        }
        __syncthreads();

        // ---- GEMM2: double-buffered in half-kt groups of 4 fragments ----
        uint4 w2c[4];
        #pragma unroll
        for (int i = 0; i < 4; i++) w2c[i] = b2w[(size_t)i * 32];

        #pragma unroll
        for (int kt2 = 0; kt2 < 4; kt2++) {
            uint32_t a0h[4], a1h[4], a0l[4], a1l[4];
            ldsm4(a0h, hBH[0] + kt2 * 32);
            ldsm4(a1h, hBH[1] + kt2 * 32);
            ldsm4(a0l, hBL[0] + kt2 * 32);
            ldsm4(a1l, hBL[1] + kt2 * 32);

            uint4 wnA[4];
            #pragma unroll
            for (int i = 0; i < 4; i++)
                wnA[i] = b2w[(size_t)(kt2 * 16 + 4 + i) * 32];

            #pragma unroll
            for (int nt = 0; nt < 4; nt++) {
                mma16816(acc2[nt],     a0h, w2c[nt].x, w2c[nt].y);
                mma16816(acc2[nt],     a0h, w2c[nt].z, w2c[nt].w);
                mma16816(acc2[nt],     a0l, w2c[nt].x, w2c[nt].y);
                mma16816(acc2[8 + nt], a1h, w2c[nt].x, w2c[nt].y);
                mma16816(acc2[8 + nt], a1h, w2c[nt].z, w2c[nt].w);
                mma16816(acc2[8 + nt], a1l, w2c[nt].x, w2c[nt].y);
            }
            uint4 wnB[4];
            if (kt2 < 3) {
                #pragma unroll
                for (int i = 0; i < 4; i++)
                    wnB[i] = b2w[(size_t)((kt2 + 1) * 16 + i) * 32];
            }
            #pragma unroll
            for (int nt = 0; nt < 4; nt++) {
                mma16816(acc2[4 + nt],  a0h, wnA[nt].x, wnA[nt].y);
                mma16816(acc2[4 + nt],  a0h, wnA[nt].z, wnA[nt].w);
                mma16816(acc2[4 + nt],  a0l, wnA[nt].x, wnA[nt].y);
                mma16816(acc2[12 + nt], a1h, wnA[nt].x, wnA[nt].y);
                mma16816(acc2[12 + nt], a1h, wnA[nt].z, wnA[nt].w);
                mma16816(acc2[12 + nt], a1l, wnA[nt].x, wnA[nt].y);
            }
            #pragma unroll
            for (int i = 0; i < 4; i++) w2c[i] = wnB[i];
        }
        __syncthreads();
    }

    // ---- epilogue: + b2 + x, NCHW store ----
    #pragma unroll
    for (int mt = 0; mt < 2; mt++) {
        #pragma unroll
        for (int half = 0; half < 2; half++) {
            int row = rg * 32 + mt * 16 + (l >> 2) + half * 8;
            size_t gpx = p0 + row;
            size_t bI = gpx / HWP, hw = gpx % HWP;
            const float* xb = x + bI * CC * HWP + hw;
            float* ob = out + bI * CC * HWP + hw;
            #pragma unroll
            for (int ntp = 0; ntp < 8; ntp++) {
                int nt = (ntp & 3) + (ntp >> 2) * 4;
                int c = cg * 64 + ((ntp < 4) ? ntp * 8 : 32 + (ntp - 4) * 8) + (l & 3) * 2;
                int ai = (ntp < 4) ? ntp : 4 + (ntp - 4);
                ai = mt * 8 + ai;
                (void)nt;
                ob[(size_t)c * HWP] =
                    acc2[ai][half * 2] + b2s[c] + xb[(size_t)c * HWP];
                ob[(size_t)(c + 1) * HWP] =
                    acc2[ai][half * 2 + 1] + b2s[c + 1] + xb[(size_t)(c + 1) * HWP];
            }
        }
    }
}

// ---------------------------------------------------------------------------
extern "C" void kernel_launch(void* const* d_in, const int* in_sizes, int n_in,
                              void* d_out, int out_size)
{
    const float* x   = (const float*)d_in[0];
    const float* c1w = (const float*)d_in[1];
    const float* c1b = (const float*)d_in[2];
    const float* bng = (const float*)d_in[3];
    const float* bnb = (const float*)d_in[4];
    const float* bnm = (const float*)d_in[5];
    const float* bnv = (const float*)d_in[6];
    const float* c2w = (const float*)d_in[7];
    const float* c2b = (const float*)d_in[8];
    const float* lnw = (const float*)d_in[9];
    const float* lnb = (const float*)d_in[10];
    const float* w1  = (const float*)d_in[11];
    const float* b1  = (const float*)d_in[12];
    const float* w2  = (const float*)d_in[13];
    const float* b2  = (const float*)d_in[14];
    float* out = (float*)d_out;

    cudaFuncSetAttribute(kernFI, cudaFuncAttributeMaxDynamicSharedMemorySize, SMEM_F);
    cudaFuncSetAttribute(kernM, cudaFuncAttributeMaxDynamicSharedMemorySize, SMEM_M);

    kernP<<<128, 256>>>(w1, w2);
    kernFI<<<BB * HH, 224, SMEM_F>>>(x, c1w, c1b, bng, bnb, bnm, bnv, c2w, c2b);
    kernM<<<NPIX / 64, 128, SMEM_M>>>(x, b1, b2, lnw, lnb, out);
}